// round 2
// baseline (speedup 1.0000x reference)
#include <cuda_runtime.h>
#include <math.h>

#define PA(py,px) (((py)+1)*10 + (px) + 1)

__device__ float d_m0[8*64*64];
__device__ float d_m1[8*64*64];
__device__ float d_m2[8*64*64];
__device__ float d_mh0[8*32*64];
__device__ float d_mh1[8*32*64];
__device__ float d_r2[8*32*64];
__device__ float d_wsum[64*9];
__device__ float d_etot[8*64*64];
__device__ int   d_idx[8*64];
__device__ float d_U[8*64*32];

// warp-per-pixel Hopfield. yin: smem [32ch][64px]; ps: smem patterns [512][32].
// r2g!=0: write 2*(y-q); else write q to qg.
__device__ __forceinline__ void hopfield_warp(const float* yin, const float* ps,
                                              float* r2g, float* qg)
{
    int t = threadIdx.x, lane = t & 31, wid = t >> 5;
    for (int j = 0; j < 8; j++) {
        int p = wid * 8 + j;
        float yv[32];
        #pragma unroll
        for (int c = 0; c < 32; c++) yv[c] = yin[c*64 + p];
        float le[16], mx = -3.4e38f;
        #pragma unroll
        for (int k = 0; k < 16; k++) {
            const float* pr = ps + (lane + 32*k)*32;
            float a = 0.f;
            #pragma unroll
            for (int c = 0; c < 32; c++) a = fmaf(yv[c], pr[c], a);
            a *= 0.17677669529663688f;
            le[k] = a; mx = fmaxf(mx, a);
        }
        #pragma unroll
        for (int o = 16; o > 0; o >>= 1) mx = fmaxf(mx, __shfl_xor_sync(~0u, mx, o));
        float ssum = 0.f, accq[32];
        #pragma unroll
        for (int c = 0; c < 32; c++) accq[c] = 0.f;
        #pragma unroll
        for (int k = 0; k < 16; k++) {
            float pe = expf(le[k] - mx);
            ssum += pe;
            const float* pr = ps + (lane + 32*k)*32;
            #pragma unroll
            for (int c = 0; c < 32; c++) accq[c] = fmaf(pe, pr[c], accq[c]);
        }
        #pragma unroll
        for (int o = 16; o > 0; o >>= 1) ssum += __shfl_xor_sync(~0u, ssum, o);
        float myq = 0.f;
        #pragma unroll
        for (int c = 0; c < 32; c++) {
            float v = accq[c];
            #pragma unroll
            for (int o = 16; o > 0; o >>= 1) v += __shfl_xor_sync(~0u, v, o);
            if (lane == c) myq = v;
        }
        float q = myq / ssum;
        if (r2g) r2g[lane*64 + p] = 2.f*(yin[lane*64 + p] - q);
        else     qg[lane*64 + p] = q;
    }
}

// ---- kernel 1: forward, masks, wsum, r2.  grid 8, 256 thr ----
__global__ void fwd_kernel(const float* x, const float* w1c, const float* b1,
                           const float* rw1a, const float* rw2a,
                           const float* rw1b, const float* rw2b,
                           const float* w2c, const float* b2, const float* pats)
{
    extern __shared__ float sm[];
    float* xs = sm;          // [64][100] padded relu'd activations
    float* ys = xs + 6400;   // [64][64] current y
    float* hs = ys + 4096;   // [32][64] relu(h_pre)
    float* yo = hs + 2048;   // [32][64] conv2 out
    float* ps = yo + 2048;   // [512][32]
    int b = blockIdx.x, t = threadIdx.x;

    for (int i = t; i < 6400; i += 256) xs[i] = 0.f;
    for (int i = t; i < 512*32; i += 256) ps[i] = pats[i];
    __syncthreads();
    for (int i = t; i < 4096; i += 256) {
        int ci = i >> 6, p = i & 63;
        xs[ci*100 + PA(p>>3, p&7)] = x[(b*64 + ci)*64 + p];
    }
    if (b == 0)
        for (int i = t; i < 576; i += 256) {
            int co = i/9, k = i%9; float s = 0.f;
            for (int ci = 0; ci < 64; ci++) s += w1c[(co*64+ci)*9 + k];
            d_wsum[co*9 + k] = s;
        }
    __syncthreads();

    { // conv1 3x3 pad1 64->64; thread tile 2co x 8px-row
        int co0 = (t >> 3)*2, row = t & 7;
        float a0[8], a1[8];
        #pragma unroll
        for (int q = 0; q < 8; q++) { a0[q] = 0.f; a1[q] = 0.f; }
        for (int ci = 0; ci < 64; ci++) {
            const float* xb = xs + ci*100;
            #pragma unroll
            for (int dy = 0; dy < 3; dy++) {
                const float* xr = xb + (row+dy)*10;
                const float* wp0 = w1c + ((co0*64+ci)*3+dy)*3;
                const float* wp1 = w1c + (((co0+1)*64+ci)*3+dy)*3;
                float w00=wp0[0], w01=wp0[1], w02=wp0[2];
                float w10=wp1[0], w11=wp1[1], w12=wp1[2];
                #pragma unroll
                for (int q = 0; q < 8; q++) {
                    float x0=xr[q], x1=xr[q+1], x2=xr[q+2];
                    a0[q] += w00*x0 + w01*x1 + w02*x2;
                    a1[q] += w10*x0 + w11*x1 + w12*x2;
                }
            }
        }
        float bb0 = b1[co0], bb1 = b1[co0+1];
        #pragma unroll
        for (int q = 0; q < 8; q++) {
            ys[co0*64 + row*8 + q]     = a0[q] + bb0;
            ys[(co0+1)*64 + row*8 + q] = a1[q] + bb1;
        }
    }
    __syncthreads();
    for (int i = t; i < 4096; i += 256) {
        int ci = i >> 6, p = i & 63;
        float v = ys[i], m = v > 0.f ? 1.f : 0.f;
        d_m0[(b*64+ci)*64 + p] = m;
        xs[ci*100 + PA(p>>3, p&7)] = v*m;
    }
    __syncthreads();

    for (int kres = 0; kres < 2; kres++) {
        const float* rw1 = kres ? rw1b : rw1a;
        const float* rw2 = kres ? rw2b : rw2a;
        float* dmh = kres ? d_mh1 : d_mh0;
        float* dm  = kres ? d_m2  : d_m1;
        { // conv3x3 64->32 on relu(y)
            int r = t >> 3, row = t & 7;
            float a[8];
            #pragma unroll
            for (int q = 0; q < 8; q++) a[q] = 0.f;
            for (int ci = 0; ci < 64; ci++) {
                const float* xb = xs + ci*100;
                #pragma unroll
                for (int dy = 0; dy < 3; dy++) {
                    const float* xr = xb + (row+dy)*10;
                    const float* wp = rw1 + ((r*64+ci)*3+dy)*3;
                    float w0=wp[0], w1=wp[1], w2=wp[2];
                    #pragma unroll
                    for (int q = 0; q < 8; q++) a[q] += w0*xr[q] + w1*xr[q+1] + w2*xr[q+2];
                }
            }
            #pragma unroll
            for (int q = 0; q < 8; q++) {
                int p = row*8 + q;
                float v = a[q], m = v > 0.f ? 1.f : 0.f;
                dmh[(b*32+r)*64 + p] = m;
                hs[r*64 + p] = v*m;
            }
        }
        __syncthreads();
        for (int i = t; i < 4096; i += 256) { // y += W2 @ h
            int ci = i >> 6, p = i & 63;
            float acc = ys[i];
            const float* w = rw2 + ci*32;
            for (int r = 0; r < 32; r++) acc += w[r]*hs[r*64 + p];
            ys[i] = acc;
        }
        __syncthreads();
        for (int i = t; i < 4096; i += 256) {
            int ci = i >> 6, p = i & 63;
            float v = ys[i], m = v > 0.f ? 1.f : 0.f;
            dm[(b*64+ci)*64 + p] = m;
            xs[ci*100 + PA(p>>3, p&7)] = v*m;
        }
        __syncthreads();
    }

    for (int i = t; i < 2048; i += 256) { // conv2 1x1 + bias
        int o = i >> 6, p = i & 63;
        float acc = b2[o];
        const float* w = w2c + o*64;
        for (int ci = 0; ci < 64; ci++) acc += w[ci]*xs[ci*100 + PA(p>>3, p&7)];
        yo[i] = acc;
    }
    __syncthreads();
    hopfield_warp(yo, ps, d_r2 + b*32*64, 0);
}

// ---- kernel 2: backward per (seed pixel s, sample b). grid (64,8), 256 thr ----
__global__ void bwd_kernel(const float* rw1a, const float* rw2a,
                           const float* rw1b, const float* rw2b, const float* w2c)
{
    extern __shared__ float sm[];
    float* gs  = sm;           // [64][100] cotangent (padded)
    float* as_ = gs + 6400;    // [32][100]
    float* w1s = as_ + 3200;   // 32*64*9
    float* w2s = w1s + 18432;  // 64*32
    int s = blockIdx.x, b = blockIdx.y, t = threadIdx.x;

    for (int i = t; i < 6400; i += 256) gs[i] = 0.f;
    for (int i = t; i < 3200; i += 256) as_[i] = 0.f;
    for (int i = t; i < 18432; i += 256) w1s[i] = rw1b[i];
    for (int i = t; i < 2048; i += 256) w2s[i] = rw2b[i];
    __syncthreads();

    if (t < 64) { // seed: g[ci,s] = m2 * conv2^T r2
        float acc = 0.f;
        for (int o = 0; o < 32; o++) acc += d_r2[(b*32+o)*64 + s] * w2c[o*64 + t];
        gs[t*100 + PA(s>>3, s&7)] = acc * d_m2[(b*64+t)*64 + s];
    }
    __syncthreads();

    for (int kres = 1; kres >= 0; kres--) {
        const float* dmh = kres ? d_mh1 : d_mh0;
        const float* dm  = kres ? d_m1  : d_m0;
        { // a[r,p] = mh * sum_ci w2[ci,r] g[ci,p]
            int r = t >> 3, row = t & 7;
            float acc[8];
            #pragma unroll
            for (int q = 0; q < 8; q++) acc[q] = 0.f;
            for (int ci = 0; ci < 64; ci++) {
                float w = w2s[ci*32 + r];
                const float* gr = gs + ci*100 + (row+1)*10 + 1;
                #pragma unroll
                for (int q = 0; q < 8; q++) acc[q] += w*gr[q];
            }
            const float* mh = dmh + (b*32+r)*64 + row*8;
            float* ar = as_ + r*100 + (row+1)*10 + 1;
            #pragma unroll
            for (int q = 0; q < 8; q++) ar[q] = acc[q]*mh[q];
        }
        __syncthreads();
        #pragma unroll
        for (int half = 0; half < 2; half++) { // g += m * W1^T a
            int ci = (t >> 3) + half*32, row = t & 7;
            float acc[8];
            #pragma unroll
            for (int q = 0; q < 8; q++) acc[q] = 0.f;
            for (int r = 0; r < 32; r++) {
                #pragma unroll
                for (int dy = 0; dy < 3; dy++) {
                    const float* ar = as_ + r*100 + (row-dy+2)*10 + 2;
                    const float* wp = w1s + ((r*64+ci)*3+dy)*3;
                    float w0=wp[0], w1=wp[1], w2=wp[2];
                    #pragma unroll
                    for (int q = 0; q < 8; q++) acc[q] += w0*ar[q] + w1*ar[q-1] + w2*ar[q-2];
                }
            }
            const float* m = dm + (b*64+ci)*64 + row*8;
            float* gr = gs + ci*100 + (row+1)*10 + 1;
            #pragma unroll
            for (int q = 0; q < 8; q++) gr[q] += acc[q]*m[q];
        }
        __syncthreads();
        if (kres == 1) {
            for (int i = t; i < 18432; i += 256) w1s[i] = rw1a[i];
            for (int i = t; i < 2048; i += 256) w2s[i] = rw2a[i];
            __syncthreads();
        }
    }

    if (t < 64) { // e_total[b,s,q] via channel-summed conv1^T
        int qy = t >> 3, qx = t & 7;
        float acc = 0.f;
        for (int co = 0; co < 64; co++) {
            const float* gb = gs + co*100;
            const float* ws = d_wsum + co*9;
            #pragma unroll
            for (int dy = 0; dy < 3; dy++) {
                const float* gr = gb + (qy-dy+2)*10 + 2;
                acc += ws[dy*3+0]*gr[qx] + ws[dy*3+1]*gr[qx-1] + ws[dy*3+2]*gr[qx-2];
            }
        }
        d_etot[(b*64+s)*64 + t] = acc;
    }
}

__global__ void argmin_kernel()
{
    int b = blockIdx.x, q = threadIdx.x;
    float best = d_etot[(b*64+0)*64 + q]; int bi = 0;
    for (int s = 1; s < 64; s++) {
        float v = d_etot[(b*64+s)*64 + q];
        if (v < best) { best = v; bi = s; }
    }
    d_idx[b*64 + q] = bi;
}

// ---- kernel 4: tangent per (input pixel i, sample b). grid (64,8), 256 thr ----
__global__ void tan_kernel(const float* x, const float* w1c,
                           const float* rw1a, const float* rw2a,
                           const float* rw1b, const float* rw2b, const float* w2c)
{
    extern __shared__ float sm[];
    float* ts  = sm;           // [64][100]
    float* tm  = ts + 6400;    // [64][100]
    float* tas = tm + 6400;    // [32][100]
    float* w1s = tas + 3200;   // 32*64*9
    float* w2s = w1s + 18432;  // 64*32
    float* xv  = w2s + 2048;   // 64
    int i = blockIdx.x, b = blockIdx.y, t = threadIdx.x;
    int iy = i >> 3, ix = i & 7;

    for (int k = t; k < 6400; k += 256) { ts[k] = 0.f; tm[k] = 0.f; }
    for (int k = t; k < 3200; k += 256) tas[k] = 0.f;
    for (int k = t; k < 18432; k += 256) w1s[k] = rw1a[k];
    for (int k = t; k < 2048; k += 256) w2s[k] = rw2a[k];
    if (t < 64) xv[t] = x[(b*64+t)*64 + i];
    __syncthreads();

    for (int task = t; task < 576; task += 256) { // conv1 of delta seed
        int co = task/9, d = task%9, dy = d/3, dx = d%3;
        int py = iy + 1 - dy, px = ix + 1 - dx;
        if (py >= 0 && py < 8 && px >= 0 && px < 8) {
            float acc = 0.f;
            for (int ci = 0; ci < 64; ci++) acc += w1c[((co*64+ci)*3+dy)*3+dx]*xv[ci];
            ts[co*100 + PA(py,px)] = acc;
        }
    }
    __syncthreads();

    for (int kres = 0; kres < 2; kres++) {
        const float* dmh = kres ? d_mh1 : d_mh0;
        const float* dm  = kres ? d_m1  : d_m0;
        for (int k = t; k < 4096; k += 256) { // tm = m * t
            int ci = k >> 6, p = k & 63;
            int pa = ci*100 + PA(p>>3, p&7);
            tm[pa] = ts[pa]*dm[(b*64+ci)*64 + p];
        }
        __syncthreads();
        { // tas = mh * conv3x3(tm)
            int r = t >> 3, row = t & 7;
            float acc[8];
            #pragma unroll
            for (int q = 0; q < 8; q++) acc[q] = 0.f;
            for (int ci = 0; ci < 64; ci++) {
                const float* xb = tm + ci*100;
                #pragma unroll
                for (int dy = 0; dy < 3; dy++) {
                    const float* xr = xb + (row+dy)*10;
                    const float* wp = w1s + ((r*64+ci)*3+dy)*3;
                    float w0=wp[0], w1=wp[1], w2=wp[2];
                    #pragma unroll
                    for (int q = 0; q < 8; q++) acc[q] += w0*xr[q] + w1*xr[q+1] + w2*xr[q+2];
                }
            }
            const float* mh = dmh + (b*32+r)*64 + row*8;
            float* ar = tas + r*100 + (row+1)*10 + 1;
            #pragma unroll
            for (int q = 0; q < 8; q++) ar[q] = acc[q]*mh[q];
        }
        __syncthreads();
        for (int k = t; k < 4096; k += 256) { // t += W2 @ tas
            int ci = k >> 6, p = k & 63;
            float acc = 0.f;
            const float* w = w2s + ci*32;
            int pa = PA(p>>3, p&7);
            for (int r = 0; r < 32; r++) acc += w[r]*tas[r*100 + pa];
            ts[ci*100 + pa] += acc;
        }
        __syncthreads();
        if (kres == 0) {
            for (int k = t; k < 18432; k += 256) w1s[k] = rw1b[k];
            for (int k = t; k < 2048; k += 256) w2s[k] = rw2b[k];
            __syncthreads();
        }
    }

    if (t < 32) { // U[b,i,o] at routed pixel m
        int m = d_idx[b*64 + i];
        int pa = PA(m>>3, m&7);
        float acc = 0.f;
        for (int ci = 0; ci < 64; ci++)
            acc += w2c[t*64+ci]*ts[ci*100+pa]*d_m2[(b*64+ci)*64 + m];
        d_U[(b*64+i)*32 + t] = acc;
    }
}

// ---- kernel 5: scatter + final hopfield. grid 8, 256 thr ----
__global__ void final_kernel(const float* pats, float* out)
{
    extern __shared__ float sm[];
    float* ym = sm;            // [32][64]
    float* ps = ym + 2048;     // [512][32]
    float* Us = ps + 16384;    // [64][32]
    int*   ix = (int*)(Us + 2048);
    int b = blockIdx.x, t = threadIdx.x;

    for (int i = t; i < 16384; i += 256) ps[i] = pats[i];
    for (int i = t; i < 2048; i += 256) Us[i] = d_U[b*2048 + i];
    if (t < 64) ix[t] = d_idx[b*64 + t];
    __syncthreads();
    for (int i = t; i < 2048; i += 256) {
        int o = i >> 6, m = i & 63;
        float acc = 0.f;
        for (int ii = 0; ii < 64; ii++)
            acc += (ix[ii] == m) ? Us[ii*32 + o] : 0.f;
        ym[o*64 + m] = acc;
    }
    __syncthreads();
    hopfield_warp(ym, ps, 0, out + b*2048);
}

extern "C" void kernel_launch(void* const* d_in, const int* in_sizes, int n_in,
                              void* d_out, int out_size)
{
    const float* x    = (const float*)d_in[0];
    const float* w1c  = (const float*)d_in[1];
    const float* b1   = (const float*)d_in[2];
    const float* rw1a = (const float*)d_in[3];
    const float* rw2a = (const float*)d_in[4];
    const float* rw1b = (const float*)d_in[5];
    const float* rw2b = (const float*)d_in[6];
    const float* w2c  = (const float*)d_in[7];
    const float* b2   = (const float*)d_in[8];
    const float* pats = (const float*)d_in[9];
    float* out = (float*)d_out;

    const int FWD = 30976*4, BWD = 30080*4, TAN = 36544*4, FIN = (20544+64)*4;
    cudaFuncSetAttribute(fwd_kernel,   cudaFuncAttributeMaxDynamicSharedMemorySize, FWD);
    cudaFuncSetAttribute(bwd_kernel,   cudaFuncAttributeMaxDynamicSharedMemorySize, BWD);
    cudaFuncSetAttribute(tan_kernel,   cudaFuncAttributeMaxDynamicSharedMemorySize, TAN);
    cudaFuncSetAttribute(final_kernel, cudaFuncAttributeMaxDynamicSharedMemorySize, FIN);

    fwd_kernel<<<8, 256, FWD>>>(x, w1c, b1, rw1a, rw2a, rw1b, rw2b, w2c, b2, pats);
    bwd_kernel<<<dim3(64,8), 256, BWD>>>(rw1a, rw2a, rw1b, rw2b, w2c);
    argmin_kernel<<<8, 64>>>();
    tan_kernel<<<dim3(64,8), 256, TAN>>>(x, w1c, rw1a, rw2a, rw1b, rw2b, w2c);
    final_kernel<<<8, 256, FIN>>>(pats, out);
}

// round 4
// speedup vs baseline: 1.3382x; 1.3382x over previous
#include <cuda_runtime.h>
#include <math.h>

#define PA12(py,px) (((py)+1)*12 + (px) + 1)

__device__ float d_m0[8*64*64];
__device__ float d_m1[8*64*64];
__device__ float d_m2[8*64*64];
__device__ float d_mh0[8*32*64];
__device__ float d_mh1[8*32*64];
__device__ float d_r2[8*32*64];
__device__ float d_wsum[64*9];
__device__ float d_etot[8*64*64];
__device__ int   d_idx[8*64];
__device__ float d_U[8*64*32];
__device__ float d_w1p[2*32*64*12];   // res conv weights padded [kres][r][ci][dy*4+dx]
__device__ float d_w1cp[64*64*12];    // conv1 weights padded

__device__ __forceinline__ void ldrow12(const float* p, float* r) {
    float4 a = *(const float4*)p;
    float4 b = *(const float4*)(p + 4);
    float4 c = *(const float4*)(p + 8);
    r[0]=a.x; r[1]=a.y; r[2]=a.z; r[3]=a.w;
    r[4]=b.x; r[5]=b.y; r[6]=b.z; r[7]=b.w;
    r[8]=c.x; r[9]=c.y; r[10]=c.z; r[11]=c.w;
}

// warp-per-pixel-group Hopfield. yin smem [32ch][64px]; ps smem [512][32].
__device__ __forceinline__ void hopfield_warp(const float* yin, const float* ps,
                                              float* r2g, float* qg, int ppw)
{
    int t = threadIdx.x, lane = t & 31, wid = t >> 5;
    for (int j = 0; j < ppw; j++) {
        int p = wid * ppw + j;
        float yv[32];
        #pragma unroll
        for (int c = 0; c < 32; c++) yv[c] = yin[c*64 + p];
        float le[16], mx = -3.4e38f;
        #pragma unroll
        for (int k = 0; k < 16; k++) {
            const float* pr = ps + (lane + 32*k)*32;
            float a = 0.f;
            #pragma unroll
            for (int c = 0; c < 32; c++) a = fmaf(yv[c], pr[c], a);
            a *= 0.17677669529663688f;
            le[k] = a; mx = fmaxf(mx, a);
        }
        #pragma unroll
        for (int o = 16; o > 0; o >>= 1) mx = fmaxf(mx, __shfl_xor_sync(~0u, mx, o));
        float ssum = 0.f, accq[32];
        #pragma unroll
        for (int c = 0; c < 32; c++) accq[c] = 0.f;
        #pragma unroll
        for (int k = 0; k < 16; k++) {
            float pe = expf(le[k] - mx);
            ssum += pe;
            const float* pr = ps + (lane + 32*k)*32;
            #pragma unroll
            for (int c = 0; c < 32; c++) accq[c] = fmaf(pe, pr[c], accq[c]);
        }
        #pragma unroll
        for (int o = 16; o > 0; o >>= 1) ssum += __shfl_xor_sync(~0u, ssum, o);
        float myq = 0.f;
        #pragma unroll
        for (int c = 0; c < 32; c++) {
            float v = accq[c];
            #pragma unroll
            for (int o = 16; o > 0; o >>= 1) v += __shfl_xor_sync(~0u, v, o);
            if (lane == c) myq = v;
        }
        float q = myq / ssum;
        if (r2g) r2g[lane*64 + p] = 2.f*(yin[lane*64 + p] - q);
        else     qg[lane*64 + p] = q;
    }
}

// ---- prep: pad weights, compute wsum ----
__global__ void __launch_bounds__(256) prep_kernel(const float* w1c, const float* rw1a, const float* rw1b)
{
    int t = blockIdx.x*blockDim.x + threadIdx.x;
    if (t < 49152) {
        int rem = t % 12, base = t / 12, dy = rem >> 2, dx = rem & 3;
        d_w1cp[t] = (dx < 3) ? w1c[base*9 + dy*3 + dx] : 0.f;
    }
    if (t < 24576) {
        int rem = t % 12, base = t / 12, dy = rem >> 2, dx = rem & 3;
        d_w1p[t]         = (dx < 3) ? rw1a[base*9 + dy*3 + dx] : 0.f;
        d_w1p[24576 + t] = (dx < 3) ? rw1b[base*9 + dy*3 + dx] : 0.f;
    }
    if (t < 576) {
        int co = t/9, k = t%9; float s = 0.f;
        for (int ci = 0; ci < 64; ci++) s += w1c[(co*64+ci)*9 + k];
        d_wsum[t] = s;
    }
}

// ---- kernel 1: forward, masks, r2. grid 8, 512 thr ----
__global__ void __launch_bounds__(512, 1) fwd_kernel(
                           const float* x, const float* b1,
                           const float* rw2a, const float* rw2b,
                           const float* w2c, const float* b2, const float* pats)
{
    extern __shared__ float sm[];
    float* xs   = sm;            // [64][120]
    float* ys   = xs + 7680;     // [64][64]
    float* hs   = ys + 4096;     // [32][64]
    float* yo   = hs + 2048;     // [32][64]
    float* ps   = yo + 2048;     // [512][32]
    float* part = ps + 16384;    // [2][32][64]
    int b = blockIdx.x, t = threadIdx.x;

    for (int i = t; i < 7680; i += 512) xs[i] = 0.f;
    for (int i = t; i < 16384; i += 512) ps[i] = pats[i];
    __syncthreads();
    for (int i = t; i < 4096; i += 512) {
        int ci = i >> 6, p = i & 63;
        xs[ci*120 + PA12(p>>3, p&7)] = x[(b*64 + ci)*64 + p];
    }
    __syncthreads();

    { // conv1 3x3 pad1 64->64
        int co = t >> 3, row = t & 7;
        float acc[8];
        #pragma unroll
        for (int q = 0; q < 8; q++) acc[q] = 0.f;
        for (int ci = 0; ci < 64; ci++) {
            const float* xb = xs + ci*120;
            #pragma unroll
            for (int dy = 0; dy < 3; dy++) {
                float xr[12]; ldrow12(xb + (row+dy)*12, xr);
                float4 w = __ldg((const float4*)(d_w1cp + (co*64+ci)*12 + dy*4));
                #pragma unroll
                for (int q = 0; q < 8; q++)
                    acc[q] += w.x*xr[q] + w.y*xr[q+1] + w.z*xr[q+2];
            }
        }
        float bb = b1[co];
        #pragma unroll
        for (int q = 0; q < 8; q++) ys[co*64 + row*8 + q] = acc[q] + bb;
    }
    __syncthreads();
    for (int i = t; i < 4096; i += 512) {
        int ci = i >> 6, p = i & 63;
        float v = ys[i], m = v > 0.f ? 1.f : 0.f;
        d_m0[(b*64+ci)*64 + p] = m;
        xs[ci*120 + PA12(p>>3, p&7)] = v*m;
    }
    __syncthreads();

    for (int kres = 0; kres < 2; kres++) {
        const float* rw2 = kres ? rw2b : rw2a;
        const float* w1p = d_w1p + kres*24576;
        float* dmh = kres ? d_mh1 : d_mh0;
        float* dm  = kres ? d_m2  : d_m1;
        { // conv3x3 64->32 split-ci over 512 threads
            int half = t >> 8, r = (t >> 3) & 31, row = t & 7;
            float acc[8];
            #pragma unroll
            for (int q = 0; q < 8; q++) acc[q] = 0.f;
            for (int cc = 0; cc < 32; cc++) {
                int ci = half*32 + cc;
                const float* xb = xs + ci*120;
                #pragma unroll
                for (int dy = 0; dy < 3; dy++) {
                    float xr[12]; ldrow12(xb + (row+dy)*12, xr);
                    float4 w = __ldg((const float4*)(w1p + (r*64+ci)*12 + dy*4));
                    #pragma unroll
                    for (int q = 0; q < 8; q++)
                        acc[q] += w.x*xr[q] + w.y*xr[q+1] + w.z*xr[q+2];
                }
            }
            #pragma unroll
            for (int q = 0; q < 8; q++) part[half*2048 + r*64 + row*8 + q] = acc[q];
        }
        __syncthreads();
        for (int k = t; k < 2048; k += 512) {
            int r = k >> 6, p = k & 63;
            float v = part[r*64 + p] + part[2048 + r*64 + p];
            float m = v > 0.f ? 1.f : 0.f;
            dmh[(b*32+r)*64 + p] = m;
            hs[k] = v*m;
        }
        __syncthreads();
        for (int k = t; k < 4096; k += 512) {
            int ci = k >> 6, p = k & 63;
            float acc = ys[k];
            #pragma unroll
            for (int rr = 0; rr < 8; rr++) {
                float4 w = __ldg((const float4*)(rw2 + ci*32 + rr*4));
                acc += w.x*hs[(rr*4+0)*64+p] + w.y*hs[(rr*4+1)*64+p]
                     + w.z*hs[(rr*4+2)*64+p] + w.w*hs[(rr*4+3)*64+p];
            }
            ys[k] = acc;
        }
        __syncthreads();
        for (int k = t; k < 4096; k += 512) {
            int ci = k >> 6, p = k & 63;
            float v = ys[k], m = v > 0.f ? 1.f : 0.f;
            dm[(b*64+ci)*64 + p] = m;
            xs[ci*120 + PA12(p>>3, p&7)] = v*m;
        }
        __syncthreads();
    }

    for (int k = t; k < 2048; k += 512) { // conv2 1x1 + bias
        int o = k >> 6, p = k & 63;
        float acc = b2[o];
        int pa = PA12(p>>3, p&7);
        #pragma unroll
        for (int cc = 0; cc < 16; cc++) {
            float4 w = __ldg((const float4*)(w2c + o*64 + cc*4));
            acc += w.x*xs[(cc*4+0)*120+pa] + w.y*xs[(cc*4+1)*120+pa]
                 + w.z*xs[(cc*4+2)*120+pa] + w.w*xs[(cc*4+3)*120+pa];
        }
        yo[k] = acc;
    }
    __syncthreads();
    hopfield_warp(yo, ps, d_r2 + b*32*64, 0, 4);
}

// ---- kernel 2: backward per (seed s, sample b). grid (64,8), 256 thr ----
__global__ void __launch_bounds__(256, 4) bwd_kernel(
                           const float* rw2a, const float* rw2b, const float* w2c)
{
    extern __shared__ float sm[];
    float* gs  = sm;           // [64][120]
    float* as_ = gs + 7680;    // [32][120]
    int s = blockIdx.x, b = blockIdx.y, t = threadIdx.x;

    for (int i = t; i < 7680; i += 256) gs[i] = 0.f;
    for (int i = t; i < 3840; i += 256) as_[i] = 0.f;
    __syncthreads();

    if (t < 64) {
        float acc = 0.f;
        for (int o = 0; o < 32; o++) acc += d_r2[(b*32+o)*64 + s] * __ldg(w2c + o*64 + t);
        gs[t*120 + PA12(s>>3, s&7)] = acc * d_m2[(b*64+t)*64 + s];
    }
    __syncthreads();

    for (int kres = 1; kres >= 0; kres--) {
        const float* dmh = kres ? d_mh1 : d_mh0;
        const float* dm  = kres ? d_m1  : d_m0;
        const float* rw2 = kres ? rw2b : rw2a;
        const float* w1p = d_w1p + kres*24576;
        { // a[r,p] = mh * sum_ci w2[ci,r]*g[ci,p]
            int r = t >> 3, row = t & 7;
            float acc[8];
            #pragma unroll
            for (int q = 0; q < 8; q++) acc[q] = 0.f;
            for (int ci = 0; ci < 64; ci++) {
                float w = __ldg(rw2 + ci*32 + r);
                float xr[12]; ldrow12(gs + ci*120 + (row+1)*12, xr);
                #pragma unroll
                for (int q = 0; q < 8; q++) acc[q] += w*xr[q+1];
            }
            const float* mh = dmh + (b*32+r)*64 + row*8;
            float* ar = as_ + r*120 + (row+1)*12 + 1;
            #pragma unroll
            for (int q = 0; q < 8; q++) ar[q] = acc[q]*mh[q];
        }
        __syncthreads();
        #pragma unroll
        for (int half = 0; half < 2; half++) { // g += m * W1^T a
            int ci = (t >> 3) + half*32, row = t & 7;
            float acc[8];
            #pragma unroll
            for (int q = 0; q < 8; q++) acc[q] = 0.f;
            for (int r = 0; r < 32; r++) {
                #pragma unroll
                for (int dy = 0; dy < 3; dy++) {
                    float xr[12]; ldrow12(as_ + r*120 + (row-dy+2)*12, xr);
                    float4 w = __ldg((const float4*)(w1p + (r*64+ci)*12 + dy*4));
                    #pragma unroll
                    for (int q = 0; q < 8; q++)
                        acc[q] += w.x*xr[q+2] + w.y*xr[q+1] + w.z*xr[q];
                }
            }
            const float* m = dm + (b*64+ci)*64 + row*8;
            float* gr = gs + ci*120 + (row+1)*12 + 1;
            #pragma unroll
            for (int q = 0; q < 8; q++) gr[q] += acc[q]*m[q];
        }
        __syncthreads();
    }

    if (t < 64) {
        int qy = t >> 3, qx = t & 7;
        float acc = 0.f;
        for (int co = 0; co < 64; co++) {
            const float* gb = gs + co*120;
            const float* ws = d_wsum + co*9;
            #pragma unroll
            for (int dy = 0; dy < 3; dy++) {
                const float* gr = gb + (qy-dy+2)*12 + 2;
                acc += ws[dy*3+0]*gr[qx] + ws[dy*3+1]*gr[qx-1] + ws[dy*3+2]*gr[qx-2];
            }
        }
        d_etot[(b*64+s)*64 + t] = acc;
    }
}

__global__ void __launch_bounds__(64) argmin_kernel()
{
    int b = blockIdx.x, q = threadIdx.x;
    float best = d_etot[(b*64+0)*64 + q]; int bi = 0;
    for (int s = 1; s < 64; s++) {
        float v = d_etot[(b*64+s)*64 + q];
        if (v < best) { best = v; bi = s; }
    }
    d_idx[b*64 + q] = bi;
}

// ---- kernel 4: tangent per (input px i, sample b). grid (64,8), 256 thr ----
__global__ void __launch_bounds__(256, 3) tan_kernel(
                           const float* x, const float* w1c,
                           const float* rw2a, const float* rw2b, const float* w2c)
{
    extern __shared__ float sm[];
    float* ts  = sm;           // [64][120]
    float* tm  = ts + 7680;    // [64][120]
    float* tas = tm + 7680;    // [32][64]
    float* xv  = tas + 2048;   // 64
    int i = blockIdx.x, b = blockIdx.y, t = threadIdx.x;
    int iy = i >> 3, ix = i & 7;

    for (int k = t; k < 7680; k += 256) { ts[k] = 0.f; tm[k] = 0.f; }
    if (t < 64) xv[t] = x[(b*64+t)*64 + i];
    __syncthreads();

    for (int task = t; task < 576; task += 256) {
        int co = task/9, d = task%9, dy = d/3, dx = d%3;
        int py = iy + 1 - dy, px = ix + 1 - dx;
        if (py >= 0 && py < 8 && px >= 0 && px < 8) {
            float acc = 0.f;
            for (int ci = 0; ci < 64; ci++) acc += __ldg(w1c + ((co*64+ci)*3+dy)*3+dx)*xv[ci];
            ts[co*120 + PA12(py,px)] = acc;
        }
    }
    __syncthreads();

    for (int kres = 0; kres < 2; kres++) {
        const float* dmh = kres ? d_mh1 : d_mh0;
        const float* dm  = kres ? d_m1  : d_m0;
        const float* rw2 = kres ? rw2b : rw2a;
        const float* w1p = d_w1p + kres*24576;
        for (int k = t; k < 4096; k += 256) {
            int ci = k >> 6, p = k & 63;
            int pa = ci*120 + PA12(p>>3, p&7);
            tm[pa] = ts[pa]*dm[(b*64+ci)*64 + p];
        }
        __syncthreads();
        { // tas = mh * conv3x3(tm)
            int r = t >> 3, row = t & 7;
            float acc[8];
            #pragma unroll
            for (int q = 0; q < 8; q++) acc[q] = 0.f;
            for (int ci = 0; ci < 64; ci++) {
                const float* xb = tm + ci*120;
                #pragma unroll
                for (int dy = 0; dy < 3; dy++) {
                    float xr[12]; ldrow12(xb + (row+dy)*12, xr);
                    float4 w = __ldg((const float4*)(w1p + (r*64+ci)*12 + dy*4));
                    #pragma unroll
                    for (int q = 0; q < 8; q++)
                        acc[q] += w.x*xr[q] + w.y*xr[q+1] + w.z*xr[q+2];
                }
            }
            const float* mh = dmh + (b*32+r)*64 + row*8;
            #pragma unroll
            for (int q = 0; q < 8; q++) tas[r*64 + row*8 + q] = acc[q]*mh[q];
        }
        __syncthreads();
        for (int k = t; k < 4096; k += 256) {
            int ci = k >> 6, p = k & 63;
            float acc = 0.f;
            #pragma unroll
            for (int rr = 0; rr < 8; rr++) {
                float4 w = __ldg((const float4*)(rw2 + ci*32 + rr*4));
                acc += w.x*tas[(rr*4+0)*64+p] + w.y*tas[(rr*4+1)*64+p]
                     + w.z*tas[(rr*4+2)*64+p] + w.w*tas[(rr*4+3)*64+p];
            }
            ts[ci*120 + PA12(p>>3, p&7)] += acc;
        }
        __syncthreads();
    }

    if (t < 32) {
        int m = d_idx[b*64 + i];
        int pa = PA12(m>>3, m&7);
        float acc = 0.f;
        for (int ci = 0; ci < 64; ci++)
            acc += __ldg(w2c + t*64 + ci)*ts[ci*120+pa]*d_m2[(b*64+ci)*64 + m];
        d_U[(b*64+i)*32 + t] = acc;
    }
}

// ---- kernel 5: scatter + final hopfield. grid 8, 256 thr ----
__global__ void __launch_bounds__(256, 1) final_kernel(const float* pats, float* out)
{
    extern __shared__ float sm[];
    float* ym = sm;            // [32][64]
    float* ps = ym + 2048;     // [512][32]
    float* Us = ps + 16384;    // [64][32]
    int*   ix = (int*)(Us + 2048);
    int b = blockIdx.x, t = threadIdx.x;

    for (int i = t; i < 16384; i += 256) ps[i] = pats[i];
    for (int i = t; i < 2048; i += 256) Us[i] = d_U[b*2048 + i];
    if (t < 64) ix[t] = d_idx[b*64 + t];
    __syncthreads();
    for (int i = t; i < 2048; i += 256) {
        int o = i >> 6, m = i & 63;
        float acc = 0.f;
        for (int ii = 0; ii < 64; ii++)
            acc += (ix[ii] == m) ? Us[ii*32 + o] : 0.f;
        ym[o*64 + m] = acc;
    }
    __syncthreads();
    hopfield_warp(ym, ps, 0, out + b*2048, 8);
}

extern "C" void kernel_launch(void* const* d_in, const int* in_sizes, int n_in,
                              void* d_out, int out_size)
{
    const float* x    = (const float*)d_in[0];
    const float* w1c  = (const float*)d_in[1];
    const float* b1   = (const float*)d_in[2];
    const float* rw1a = (const float*)d_in[3];
    const float* rw2a = (const float*)d_in[4];
    const float* rw1b = (const float*)d_in[5];
    const float* rw2b = (const float*)d_in[6];
    const float* w2c  = (const float*)d_in[7];
    const float* b2   = (const float*)d_in[8];
    const float* pats = (const float*)d_in[9];
    float* out = (float*)d_out;

    const int FWD = 36352*4;
    const int BWD = 11520*4;
    const int TAN = 17472*4;
    const int FIN = (2048+16384+2048+64)*4;
    cudaFuncSetAttribute(fwd_kernel,   cudaFuncAttributeMaxDynamicSharedMemorySize, FWD);
    cudaFuncSetAttribute(bwd_kernel,   cudaFuncAttributeMaxDynamicSharedMemorySize, BWD);
    cudaFuncSetAttribute(tan_kernel,   cudaFuncAttributeMaxDynamicSharedMemorySize, TAN);
    cudaFuncSetAttribute(final_kernel, cudaFuncAttributeMaxDynamicSharedMemorySize, FIN);

    prep_kernel<<<192, 256>>>(w1c, rw1a, rw1b);
    fwd_kernel<<<8, 512, FWD>>>(x, b1, rw2a, rw2b, w2c, b2, pats);
    bwd_kernel<<<dim3(64,8), 256, BWD>>>(rw2a, rw2b, w2c);
    argmin_kernel<<<8, 64>>>();
    tan_kernel<<<dim3(64,8), 256, TAN>>>(x, w1c, rw2a, rw2b, w2c);
    final_kernel<<<8, 256, FIN>>>(pats, out);
}

// round 5
// speedup vs baseline: 1.4018x; 1.0475x over previous
#include <cuda_runtime.h>
#include <math.h>

#define PA12(py,px) (((py)+1)*12 + (px) + 1)

__device__ float d_m0[8*64*64];
__device__ float d_m1[8*64*64];
__device__ float d_m2[8*64*64];
__device__ float d_mh0[8*32*64];
__device__ float d_mh1[8*32*64];
__device__ float d_r2[8*32*64];
__device__ float d_wsum[64*9];
__device__ float d_etot[8*64*64];
__device__ float d_V[8*64*32*64];     // [b][i][o][p] tangent outputs at all pixels
__device__ float d_w1p[2*32*64*12];   // res conv weights padded [kres][r][ci][dy*4+dx]
__device__ float d_w1cp[64*64*12];    // conv1 weights padded

__device__ __forceinline__ void ldrow12(const float* p, float* r) {
    float4 a = *(const float4*)p;
    float4 b = *(const float4*)(p + 4);
    float4 c = *(const float4*)(p + 8);
    r[0]=a.x; r[1]=a.y; r[2]=a.z; r[3]=a.w;
    r[4]=b.x; r[5]=b.y; r[6]=b.z; r[7]=b.w;
    r[8]=c.x; r[9]=c.y; r[10]=c.z; r[11]=c.w;
}

// warp-per-pixel-group Hopfield. yin smem [32ch][64px]; ps smem [512][32].
__device__ __forceinline__ void hopfield_warp(const float* yin, const float* ps,
                                              float* r2g, float* qg, int ppw)
{
    int t = threadIdx.x, lane = t & 31, wid = t >> 5;
    for (int j = 0; j < ppw; j++) {
        int p = wid * ppw + j;
        float yv[32];
        #pragma unroll
        for (int c = 0; c < 32; c++) yv[c] = yin[c*64 + p];
        float le[16], mx = -3.4e38f;
        #pragma unroll
        for (int k = 0; k < 16; k++) {
            const float* pr = ps + (lane + 32*k)*32;
            float a = 0.f;
            #pragma unroll
            for (int c = 0; c < 32; c++) a = fmaf(yv[c], pr[c], a);
            a *= 0.17677669529663688f;
            le[k] = a; mx = fmaxf(mx, a);
        }
        #pragma unroll
        for (int o = 16; o > 0; o >>= 1) mx = fmaxf(mx, __shfl_xor_sync(~0u, mx, o));
        float ssum = 0.f, accq[32];
        #pragma unroll
        for (int c = 0; c < 32; c++) accq[c] = 0.f;
        #pragma unroll
        for (int k = 0; k < 16; k++) {
            float pe = expf(le[k] - mx);
            ssum += pe;
            const float* pr = ps + (lane + 32*k)*32;
            #pragma unroll
            for (int c = 0; c < 32; c++) accq[c] = fmaf(pe, pr[c], accq[c]);
        }
        #pragma unroll
        for (int o = 16; o > 0; o >>= 1) ssum += __shfl_xor_sync(~0u, ssum, o);
        float myq = 0.f;
        #pragma unroll
        for (int c = 0; c < 32; c++) {
            float v = accq[c];
            #pragma unroll
            for (int o = 16; o > 0; o >>= 1) v += __shfl_xor_sync(~0u, v, o);
            if (lane == c) myq = v;
        }
        float q = myq / ssum;
        if (r2g) r2g[lane*64 + p] = 2.f*(yin[lane*64 + p] - q);
        else     qg[lane*64 + p] = q;
    }
}

// ---- prep: pad weights, compute wsum ----
__global__ void __launch_bounds__(256) prep_kernel(const float* w1c, const float* rw1a, const float* rw1b)
{
    int t = blockIdx.x*blockDim.x + threadIdx.x;
    if (t < 49152) {
        int rem = t % 12, base = t / 12, dy = rem >> 2, dx = rem & 3;
        d_w1cp[t] = (dx < 3) ? w1c[base*9 + dy*3 + dx] : 0.f;
    }
    if (t < 24576) {
        int rem = t % 12, base = t / 12, dy = rem >> 2, dx = rem & 3;
        d_w1p[t]         = (dx < 3) ? rw1a[base*9 + dy*3 + dx] : 0.f;
        d_w1p[24576 + t] = (dx < 3) ? rw1b[base*9 + dy*3 + dx] : 0.f;
    }
    if (t < 576) {
        int co = t/9, k = t%9; float s = 0.f;
        for (int ci = 0; ci < 64; ci++) s += w1c[(co*64+ci)*9 + k];
        d_wsum[t] = s;
    }
}

// ---- kernel 1: forward, masks, r2. grid 8, 512 thr ----
__global__ void __launch_bounds__(512, 1) fwd_kernel(
                           const float* x, const float* b1,
                           const float* rw2a, const float* rw2b,
                           const float* w2c, const float* b2, const float* pats)
{
    extern __shared__ float sm[];
    float* xs   = sm;            // [64][120]
    float* ys   = xs + 7680;     // [64][64]
    float* hs   = ys + 4096;     // [32][64]
    float* yo   = hs + 2048;     // [32][64]
    float* ps   = yo + 2048;     // [512][32]
    float* part = ps + 16384;    // [2][32][64]
    int b = blockIdx.x, t = threadIdx.x;

    for (int i = t; i < 7680; i += 512) xs[i] = 0.f;
    for (int i = t; i < 16384; i += 512) ps[i] = pats[i];
    __syncthreads();
    for (int i = t; i < 4096; i += 512) {
        int ci = i >> 6, p = i & 63;
        xs[ci*120 + PA12(p>>3, p&7)] = x[(b*64 + ci)*64 + p];
    }
    __syncthreads();

    { // conv1 3x3 pad1 64->64
        int co = t >> 3, row = t & 7;
        float acc[8];
        #pragma unroll
        for (int q = 0; q < 8; q++) acc[q] = 0.f;
        for (int ci = 0; ci < 64; ci++) {
            const float* xb = xs + ci*120;
            #pragma unroll
            for (int dy = 0; dy < 3; dy++) {
                float xr[12]; ldrow12(xb + (row+dy)*12, xr);
                float4 w = __ldg((const float4*)(d_w1cp + (co*64+ci)*12 + dy*4));
                #pragma unroll
                for (int q = 0; q < 8; q++)
                    acc[q] += w.x*xr[q] + w.y*xr[q+1] + w.z*xr[q+2];
            }
        }
        float bb = b1[co];
        #pragma unroll
        for (int q = 0; q < 8; q++) ys[co*64 + row*8 + q] = acc[q] + bb;
    }
    __syncthreads();
    for (int i = t; i < 4096; i += 512) {
        int ci = i >> 6, p = i & 63;
        float v = ys[i], m = v > 0.f ? 1.f : 0.f;
        d_m0[(b*64+ci)*64 + p] = m;
        xs[ci*120 + PA12(p>>3, p&7)] = v*m;
    }
    __syncthreads();

    for (int kres = 0; kres < 2; kres++) {
        const float* rw2 = kres ? rw2b : rw2a;
        const float* w1p = d_w1p + kres*24576;
        float* dmh = kres ? d_mh1 : d_mh0;
        float* dm  = kres ? d_m2  : d_m1;
        { // conv3x3 64->32 split-ci over 512 threads
            int half = t >> 8, r = (t >> 3) & 31, row = t & 7;
            float acc[8];
            #pragma unroll
            for (int q = 0; q < 8; q++) acc[q] = 0.f;
            for (int cc = 0; cc < 32; cc++) {
                int ci = half*32 + cc;
                const float* xb = xs + ci*120;
                #pragma unroll
                for (int dy = 0; dy < 3; dy++) {
                    float xr[12]; ldrow12(xb + (row+dy)*12, xr);
                    float4 w = __ldg((const float4*)(w1p + (r*64+ci)*12 + dy*4));
                    #pragma unroll
                    for (int q = 0; q < 8; q++)
                        acc[q] += w.x*xr[q] + w.y*xr[q+1] + w.z*xr[q+2];
                }
            }
            #pragma unroll
            for (int q = 0; q < 8; q++) part[half*2048 + r*64 + row*8 + q] = acc[q];
        }
        __syncthreads();
        for (int k = t; k < 2048; k += 512) {
            int r = k >> 6, p = k & 63;
            float v = part[r*64 + p] + part[2048 + r*64 + p];
            float m = v > 0.f ? 1.f : 0.f;
            dmh[(b*32+r)*64 + p] = m;
            hs[k] = v*m;
        }
        __syncthreads();
        for (int k = t; k < 4096; k += 512) {
            int ci = k >> 6, p = k & 63;
            float acc = ys[k];
            #pragma unroll
            for (int rr = 0; rr < 8; rr++) {
                float4 w = __ldg((const float4*)(rw2 + ci*32 + rr*4));
                acc += w.x*hs[(rr*4+0)*64+p] + w.y*hs[(rr*4+1)*64+p]
                     + w.z*hs[(rr*4+2)*64+p] + w.w*hs[(rr*4+3)*64+p];
            }
            ys[k] = acc;
        }
        __syncthreads();
        for (int k = t; k < 4096; k += 512) {
            int ci = k >> 6, p = k & 63;
            float v = ys[k], m = v > 0.f ? 1.f : 0.f;
            dm[(b*64+ci)*64 + p] = m;
            xs[ci*120 + PA12(p>>3, p&7)] = v*m;
        }
        __syncthreads();
    }

    for (int k = t; k < 2048; k += 512) { // conv2 1x1 + bias
        int o = k >> 6, p = k & 63;
        float acc = b2[o];
        int pa = PA12(p>>3, p&7);
        #pragma unroll
        for (int cc = 0; cc < 16; cc++) {
            float4 w = __ldg((const float4*)(w2c + o*64 + cc*4));
            acc += w.x*xs[(cc*4+0)*120+pa] + w.y*xs[(cc*4+1)*120+pa]
                 + w.z*xs[(cc*4+2)*120+pa] + w.w*xs[(cc*4+3)*120+pa];
        }
        yo[k] = acc;
    }
    __syncthreads();
    hopfield_warp(yo, ps, d_r2 + b*32*64, 0, 4);
}

// ---- kernel 2: merged per-seed backward (z=0) + tangent (z=1). grid (64,8,2), 256 thr ----
__global__ void __launch_bounds__(256, 4) seed_kernel(
                           const float* x, const float* w1c,
                           const float* rw2a, const float* rw2b, const float* w2c)
{
    extern __shared__ float sm[];
    int t = threadIdx.x, b = blockIdx.y;

    if (blockIdx.z == 0) {
        // ======== backward body: seed pixel s -> e_total[b,s,:] ========
        float* gs  = sm;           // [64][120]
        float* as_ = gs + 7680;    // [32][120]
        int s = blockIdx.x;

        for (int i = t; i < 7680; i += 256) gs[i] = 0.f;
        for (int i = t; i < 3840; i += 256) as_[i] = 0.f;
        __syncthreads();

        if (t < 64) {
            float acc = 0.f;
            for (int o = 0; o < 32; o++) acc += d_r2[(b*32+o)*64 + s] * __ldg(w2c + o*64 + t);
            gs[t*120 + PA12(s>>3, s&7)] = acc * d_m2[(b*64+t)*64 + s];
        }
        __syncthreads();

        for (int kres = 1; kres >= 0; kres--) {
            const float* dmh = kres ? d_mh1 : d_mh0;
            const float* dm  = kres ? d_m1  : d_m0;
            const float* rw2 = kres ? rw2b : rw2a;
            const float* w1p = d_w1p + kres*24576;
            { // a[r,p] = mh * sum_ci w2[ci,r]*g[ci,p]
                int r = t >> 3, row = t & 7;
                float acc[8];
                #pragma unroll
                for (int q = 0; q < 8; q++) acc[q] = 0.f;
                for (int ci = 0; ci < 64; ci++) {
                    float w = __ldg(rw2 + ci*32 + r);
                    float xr[12]; ldrow12(gs + ci*120 + (row+1)*12, xr);
                    #pragma unroll
                    for (int q = 0; q < 8; q++) acc[q] += w*xr[q+1];
                }
                const float* mh = dmh + (b*32+r)*64 + row*8;
                float* ar = as_ + r*120 + (row+1)*12 + 1;
                #pragma unroll
                for (int q = 0; q < 8; q++) ar[q] = acc[q]*mh[q];
            }
            __syncthreads();
            #pragma unroll
            for (int half = 0; half < 2; half++) { // g += m * W1^T a
                int ci = (t >> 3) + half*32, row = t & 7;
                float acc[8];
                #pragma unroll
                for (int q = 0; q < 8; q++) acc[q] = 0.f;
                for (int r = 0; r < 32; r++) {
                    #pragma unroll
                    for (int dy = 0; dy < 3; dy++) {
                        float xr[12]; ldrow12(as_ + r*120 + (row-dy+2)*12, xr);
                        float4 w = __ldg((const float4*)(w1p + (r*64+ci)*12 + dy*4));
                        #pragma unroll
                        for (int q = 0; q < 8; q++)
                            acc[q] += w.x*xr[q+2] + w.y*xr[q+1] + w.z*xr[q];
                    }
                }
                const float* m = dm + (b*64+ci)*64 + row*8;
                float* gr = gs + ci*120 + (row+1)*12 + 1;
                #pragma unroll
                for (int q = 0; q < 8; q++) gr[q] += acc[q]*m[q];
            }
            __syncthreads();
        }

        if (t < 64) {
            int qy = t >> 3, qx = t & 7;
            float acc = 0.f;
            for (int co = 0; co < 64; co++) {
                const float* gb = gs + co*120;
                const float* ws = d_wsum + co*9;
                #pragma unroll
                for (int dy = 0; dy < 3; dy++) {
                    const float* gr = gb + (qy-dy+2)*12 + 2;
                    acc += ws[dy*3+0]*gr[qx] + ws[dy*3+1]*gr[qx-1] + ws[dy*3+2]*gr[qx-2];
                }
            }
            d_etot[(b*64+s)*64 + t] = acc;
        }
    } else {
        // ======== tangent body: input pixel i -> V[b,i,:,:] ========
        float* ts  = sm;           // [64][64] (pointwise only -> unpadded)
        float* tm  = ts + 4096;    // [64][120] conv input (padded)
        float* tas = tm + 7680;    // [32][64]
        float* xv  = tas + 2048;   // 64
        int i = blockIdx.x;
        int iy = i >> 3, ix = i & 7;

        for (int k = t; k < 4096; k += 256) ts[k] = 0.f;
        for (int k = t; k < 7680; k += 256) tm[k] = 0.f;
        if (t < 64) xv[t] = x[(b*64+t)*64 + i];
        __syncthreads();

        for (int task = t; task < 576; task += 256) { // conv1 of delta seed
            int co = task/9, d = task%9, dy = d/3, dx = d%3;
            int py = iy + 1 - dy, px = ix + 1 - dx;
            if (py >= 0 && py < 8 && px >= 0 && px < 8) {
                float acc = 0.f;
                for (int ci = 0; ci < 64; ci++) acc += __ldg(w1c + ((co*64+ci)*3+dy)*3+dx)*xv[ci];
                ts[co*64 + py*8 + px] = acc;
            }
        }
        __syncthreads();

        for (int kres = 0; kres < 2; kres++) {
            const float* dmh = kres ? d_mh1 : d_mh0;
            const float* dm  = kres ? d_m1  : d_m0;
            const float* rw2 = kres ? rw2b : rw2a;
            const float* w1p = d_w1p + kres*24576;
            for (int k = t; k < 4096; k += 256) { // tm = m * t (into padded buf)
                int ci = k >> 6, p = k & 63;
                tm[ci*120 + PA12(p>>3, p&7)] = ts[k]*dm[(b*64+ci)*64 + p];
            }
            __syncthreads();
            { // tas = mh * conv3x3(tm)
                int r = t >> 3, row = t & 7;
                float acc[8];
                #pragma unroll
                for (int q = 0; q < 8; q++) acc[q] = 0.f;
                for (int ci = 0; ci < 64; ci++) {
                    const float* xb = tm + ci*120;
                    #pragma unroll
                    for (int dy = 0; dy < 3; dy++) {
                        float xr[12]; ldrow12(xb + (row+dy)*12, xr);
                        float4 w = __ldg((const float4*)(w1p + (r*64+ci)*12 + dy*4));
                        #pragma unroll
                        for (int q = 0; q < 8; q++)
                            acc[q] += w.x*xr[q] + w.y*xr[q+1] + w.z*xr[q+2];
                    }
                }
                const float* mh = dmh + (b*32+r)*64 + row*8;
                #pragma unroll
                for (int q = 0; q < 8; q++) tas[r*64 + row*8 + q] = acc[q]*mh[q];
            }
            __syncthreads();
            for (int k = t; k < 4096; k += 256) { // ts += W2 @ tas
                int p = k & 63;
                float acc = 0.f;
                const float* rwb = rw2 + (k >> 6)*32;
                #pragma unroll
                for (int rr = 0; rr < 8; rr++) {
                    float4 w = __ldg((const float4*)(rwb + rr*4));
                    acc += w.x*tas[(rr*4+0)*64+p] + w.y*tas[(rr*4+1)*64+p]
                         + w.z*tas[(rr*4+2)*64+p] + w.w*tas[(rr*4+3)*64+p];
                }
                ts[k] += acc;
            }
            __syncthreads();
        }

        // masked final tangent into tm (reuse as [64][64])
        for (int k = t; k < 4096; k += 256) {
            int ci = k >> 6, p = k & 63;
            tm[k] = ts[k]*d_m2[(b*64+ci)*64 + p];
        }
        __syncthreads();
        // V[b,i,o,p] = sum_ci w2c[o,ci] * tm[ci,p]
        for (int k = t; k < 2048; k += 256) {
            int o = k >> 6, p = k & 63;
            float acc = 0.f;
            #pragma unroll
            for (int cc = 0; cc < 16; cc++) {
                float4 w = __ldg((const float4*)(w2c + o*64 + cc*4));
                acc += w.x*tm[(cc*4+0)*64+p] + w.y*tm[(cc*4+1)*64+p]
                     + w.z*tm[(cc*4+2)*64+p] + w.w*tm[(cc*4+3)*64+p];
            }
            d_V[((b*64+i)*32 + o)*64 + p] = acc;
        }
    }
}

// ---- kernel 3: argmin + gather + scatter + final hopfield. grid 8, 256 thr ----
__global__ void __launch_bounds__(256, 1) final_kernel(const float* pats, float* out)
{
    extern __shared__ float sm[];
    float* ym = sm;            // [32][64]
    float* ps = ym + 2048;     // [512][32]
    float* Us = ps + 16384;    // [64][32]
    int*   ix = (int*)(Us + 2048);   // 64
    int b = blockIdx.x, t = threadIdx.x;

    for (int i = t; i < 16384; i += 256) ps[i] = pats[i];
    if (t < 64) { // argmin over seed pixel s for input pixel q=t
        float best = d_etot[(b*64+0)*64 + t]; int bi = 0;
        for (int s = 1; s < 64; s++) {
            float v = d_etot[(b*64+s)*64 + t];
            if (v < best) { best = v; bi = s; }
        }
        ix[t] = bi;
    }
    __syncthreads();
    for (int k = t; k < 2048; k += 256) { // gather routed pixel
        int i = k >> 5, o = k & 31;
        Us[k] = d_V[((b*64+i)*32 + o)*64 + ix[i]];
    }
    __syncthreads();
    for (int k = t; k < 2048; k += 256) { // scatter-add into y_masked
        int o = k >> 6, m = k & 63;
        float acc = 0.f;
        for (int ii = 0; ii < 64; ii++)
            acc += (ix[ii] == m) ? Us[ii*32 + o] : 0.f;
        ym[o*64 + m] = acc;
    }
    __syncthreads();
    hopfield_warp(ym, ps, 0, out + b*2048, 8);
}

extern "C" void kernel_launch(void* const* d_in, const int* in_sizes, int n_in,
                              void* d_out, int out_size)
{
    const float* x    = (const float*)d_in[0];
    const float* w1c  = (const float*)d_in[1];
    const float* b1   = (const float*)d_in[2];
    const float* rw1a = (const float*)d_in[3];
    const float* rw2a = (const float*)d_in[4];
    const float* rw1b = (const float*)d_in[5];
    const float* rw2b = (const float*)d_in[6];
    const float* w2c  = (const float*)d_in[7];
    const float* b2   = (const float*)d_in[8];
    const float* pats = (const float*)d_in[9];
    float* out = (float*)d_out;

    const int FWD  = 36352*4;            // 145 KB
    const int SEED = 13888*4;            // 55.5 KB -> 4 CTAs/SM
    const int FIN  = (2048+16384+2048+64)*4;
    cudaFuncSetAttribute(fwd_kernel,   cudaFuncAttributeMaxDynamicSharedMemorySize, FWD);
    cudaFuncSetAttribute(seed_kernel,  cudaFuncAttributeMaxDynamicSharedMemorySize, SEED);
    cudaFuncSetAttribute(final_kernel, cudaFuncAttributeMaxDynamicSharedMemorySize, FIN);

    prep_kernel<<<192, 256>>>(w1c, rw1a, rw1b);
    fwd_kernel<<<8, 512, FWD>>>(x, b1, rw2a, rw2b, w2c, b2, pats);
    seed_kernel<<<dim3(64,8,2), 256, SEED>>>(x, w1c, rw2a, rw2b, w2c);
    final_kernel<<<8, 256, FIN>>>(pats, out);
}

// round 6
// speedup vs baseline: 1.6821x; 1.2000x over previous
#include <cuda_runtime.h>
#include <math.h>

#define PA12(py,px) (((py)+1)*12 + (px) + 1)

__device__ float d_m0[8*64*64];
__device__ float d_m1[8*64*64];
__device__ float d_m2[8*64*64];
__device__ float d_mh0[8*32*64];
__device__ float d_mh1[8*32*64];
__device__ float d_r2[8*32*64];
__device__ float d_yo[8*32*64];
__device__ float d_ym[8*32*64];
__device__ float d_wsum[64*9];
__device__ float d_etot[8*64*64];
__device__ float d_V[8*64*32*64];     // [b][i][o][p]
__device__ float d_w1p[2*32*64*12];
__device__ float d_w1cp[64*64*12];

__device__ __forceinline__ void ldrow12(const float* p, float* r) {
    float4 a = *(const float4*)p;
    float4 b = *(const float4*)(p + 4);
    float4 c = *(const float4*)(p + 8);
    r[0]=a.x; r[1]=a.y; r[2]=a.z; r[3]=a.w;
    r[4]=b.x; r[5]=b.y; r[6]=b.z; r[7]=b.w;
    r[8]=c.x; r[9]=c.y; r[10]=c.z; r[11]=c.w;
}

// ---- prep: pad weights, compute wsum ----
__global__ void __launch_bounds__(256) prep_kernel(const float* w1c, const float* rw1a, const float* rw1b)
{
    int t = blockIdx.x*blockDim.x + threadIdx.x;
    if (t < 49152) {
        int rem = t % 12, base = t / 12, dy = rem >> 2, dx = rem & 3;
        d_w1cp[t] = (dx < 3) ? w1c[base*9 + dy*3 + dx] : 0.f;
    }
    if (t < 24576) {
        int rem = t % 12, base = t / 12, dy = rem >> 2, dx = rem & 3;
        d_w1p[t]         = (dx < 3) ? rw1a[base*9 + dy*3 + dx] : 0.f;
        d_w1p[24576 + t] = (dx < 3) ? rw1b[base*9 + dy*3 + dx] : 0.f;
    }
    if (t < 576) {
        int co = t/9, k = t%9; float s = 0.f;
        for (int ci = 0; ci < 64; ci++) s += w1c[(co*64+ci)*9 + k];
        d_wsum[t] = s;
    }
}

// ---- hopfield: grid 64 (8 samples x 8 CTAs), 256 thr, one warp per pixel ----
// mode 0: dst = 2*(src - q)   (r2 from yo)
// mode 1: dst = q             (final output from ym)
__global__ void __launch_bounds__(256) hop_kernel(const float* __restrict__ src,
                                                  const float* __restrict__ pats,
                                                  float* __restrict__ dst, int mode)
{
    extern __shared__ float sm[];
    float* ps  = sm;            // [512][32]
    float* red = ps + 16384;    // [8][32][33]
    int t = threadIdx.x, lane = t & 31, wid = t >> 5;
    int b = blockIdx.x >> 3, p = (blockIdx.x & 7)*8 + wid;

    for (int i = t; i < 16384; i += 256) ps[i] = pats[i];
    __syncthreads();

    const float* yb = src + b*2048;   // [32][64]
    float yv[32];
    #pragma unroll
    for (int c = 0; c < 32; c++) yv[c] = yb[c*64 + p];

    float le[16], mx = -3.4e38f;
    #pragma unroll
    for (int k = 0; k < 16; k++) {
        const float* pr = ps + (lane + 32*k)*32;
        float a = 0.f;
        #pragma unroll
        for (int c = 0; c < 32; c++) a = fmaf(yv[c], pr[c], a);
        a *= 0.17677669529663688f;
        le[k] = a; mx = fmaxf(mx, a);
    }
    #pragma unroll
    for (int o = 16; o > 0; o >>= 1) mx = fmaxf(mx, __shfl_xor_sync(~0u, mx, o));

    float ssum = 0.f, accq[32];
    #pragma unroll
    for (int c = 0; c < 32; c++) accq[c] = 0.f;
    #pragma unroll
    for (int k = 0; k < 16; k++) {
        float pe = expf(le[k] - mx);
        ssum += pe;
        const float* pr = ps + (lane + 32*k)*32;
        #pragma unroll
        for (int c = 0; c < 32; c++) accq[c] = fmaf(pe, pr[c], accq[c]);
    }
    #pragma unroll
    for (int o = 16; o > 0; o >>= 1) ssum += __shfl_xor_sync(~0u, ssum, o);

    // smem transpose reduction: lane writes its accq row; lane c sums column c
    float* rw = red + wid*1056;
    #pragma unroll
    for (int c = 0; c < 32; c++) rw[lane*33 + c] = accq[c];
    __syncwarp();
    float colsum = 0.f;
    #pragma unroll
    for (int l = 0; l < 32; l++) colsum += rw[l*33 + lane];
    float q = colsum / ssum;

    if (mode == 0) dst[b*2048 + lane*64 + p] = 2.f*(yv[lane] - q);
    else           dst[b*2048 + lane*64 + p] = q;
}

// ---- kernel 1: forward conv stack, masks, yo. grid 8, 512 thr ----
__global__ void __launch_bounds__(512, 1) fwd_kernel(
                           const float* x, const float* b1,
                           const float* rw2a, const float* rw2b,
                           const float* w2c, const float* b2)
{
    extern __shared__ float sm[];
    float* xs   = sm;            // [64][120]
    float* ys   = xs + 7680;     // [64][64]
    float* hs   = ys + 4096;     // [32][64]
    float* part = hs + 2048;     // [2][32][64]
    int b = blockIdx.x, t = threadIdx.x;

    for (int i = t; i < 7680; i += 512) xs[i] = 0.f;
    __syncthreads();
    for (int i = t; i < 4096; i += 512) {
        int ci = i >> 6, p = i & 63;
        xs[ci*120 + PA12(p>>3, p&7)] = x[(b*64 + ci)*64 + p];
    }
    __syncthreads();

    { // conv1 3x3 pad1 64->64
        int co = t >> 3, row = t & 7;
        float acc[8];
        #pragma unroll
        for (int q = 0; q < 8; q++) acc[q] = 0.f;
        for (int ci = 0; ci < 64; ci++) {
            const float* xb = xs + ci*120;
            #pragma unroll
            for (int dy = 0; dy < 3; dy++) {
                float xr[12]; ldrow12(xb + (row+dy)*12, xr);
                float4 w = __ldg((const float4*)(d_w1cp + (co*64+ci)*12 + dy*4));
                #pragma unroll
                for (int q = 0; q < 8; q++)
                    acc[q] += w.x*xr[q] + w.y*xr[q+1] + w.z*xr[q+2];
            }
        }
        float bb = b1[co];
        #pragma unroll
        for (int q = 0; q < 8; q++) ys[co*64 + row*8 + q] = acc[q] + bb;
    }
    __syncthreads();
    for (int i = t; i < 4096; i += 512) {
        int ci = i >> 6, p = i & 63;
        float v = ys[i], m = v > 0.f ? 1.f : 0.f;
        d_m0[(b*64+ci)*64 + p] = m;
        xs[ci*120 + PA12(p>>3, p&7)] = v*m;
    }
    __syncthreads();

    for (int kres = 0; kres < 2; kres++) {
        const float* rw2 = kres ? rw2b : rw2a;
        const float* w1p = d_w1p + kres*24576;
        float* dmh = kres ? d_mh1 : d_mh0;
        float* dm  = kres ? d_m2  : d_m1;
        { // conv3x3 64->32 split-ci
            int half = t >> 8, r = (t >> 3) & 31, row = t & 7;
            float acc[8];
            #pragma unroll
            for (int q = 0; q < 8; q++) acc[q] = 0.f;
            for (int cc = 0; cc < 32; cc++) {
                int ci = half*32 + cc;
                const float* xb = xs + ci*120;
                #pragma unroll
                for (int dy = 0; dy < 3; dy++) {
                    float xr[12]; ldrow12(xb + (row+dy)*12, xr);
                    float4 w = __ldg((const float4*)(w1p + (r*64+ci)*12 + dy*4));
                    #pragma unroll
                    for (int q = 0; q < 8; q++)
                        acc[q] += w.x*xr[q] + w.y*xr[q+1] + w.z*xr[q+2];
                }
            }
            #pragma unroll
            for (int q = 0; q < 8; q++) part[half*2048 + r*64 + row*8 + q] = acc[q];
        }
        __syncthreads();
        for (int k = t; k < 2048; k += 512) {
            int r = k >> 6, p = k & 63;
            float v = part[r*64 + p] + part[2048 + r*64 + p];
            float m = v > 0.f ? 1.f : 0.f;
            dmh[(b*32+r)*64 + p] = m;
            hs[k] = v*m;
        }
        __syncthreads();
        for (int k = t; k < 4096; k += 512) {
            int ci = k >> 6, p = k & 63;
            float acc = ys[k];
            #pragma unroll
            for (int rr = 0; rr < 8; rr++) {
                float4 w = __ldg((const float4*)(rw2 + ci*32 + rr*4));
                acc += w.x*hs[(rr*4+0)*64+p] + w.y*hs[(rr*4+1)*64+p]
                     + w.z*hs[(rr*4+2)*64+p] + w.w*hs[(rr*4+3)*64+p];
            }
            ys[k] = acc;
        }
        __syncthreads();
        for (int k = t; k < 4096; k += 512) {
            int ci = k >> 6, p = k & 63;
            float v = ys[k], m = v > 0.f ? 1.f : 0.f;
            dm[(b*64+ci)*64 + p] = m;
            xs[ci*120 + PA12(p>>3, p&7)] = v*m;
        }
        __syncthreads();
    }

    for (int k = t; k < 2048; k += 512) { // conv2 1x1 + bias -> global yo
        int o = k >> 6, p = k & 63;
        float acc = b2[o];
        int pa = PA12(p>>3, p&7);
        #pragma unroll
        for (int cc = 0; cc < 16; cc++) {
            float4 w = __ldg((const float4*)(w2c + o*64 + cc*4));
            acc += w.x*xs[(cc*4+0)*120+pa] + w.y*xs[(cc*4+1)*120+pa]
                 + w.z*xs[(cc*4+2)*120+pa] + w.w*xs[(cc*4+3)*120+pa];
        }
        d_yo[b*2048 + k] = acc;
    }
}

// ---- kernel 2: merged per-seed backward (z=0) + tangent (z=1). grid (64,8,2), 256 thr ----
__global__ void __launch_bounds__(256, 4) seed_kernel(
                           const float* x, const float* w1c,
                           const float* rw2a, const float* rw2b, const float* w2c)
{
    extern __shared__ float sm[];
    int t = threadIdx.x, b = blockIdx.y;

    if (blockIdx.z == 0) {
        // ======== backward body ========
        float* gs  = sm;           // [64][120]
        float* as_ = gs + 7680;    // [32][120]
        int s = blockIdx.x;

        for (int i = t; i < 7680; i += 256) gs[i] = 0.f;
        for (int i = t; i < 3840; i += 256) as_[i] = 0.f;
        __syncthreads();

        if (t < 64) {
            float acc = 0.f;
            for (int o = 0; o < 32; o++) acc += d_r2[(b*32+o)*64 + s] * __ldg(w2c + o*64 + t);
            gs[t*120 + PA12(s>>3, s&7)] = acc * d_m2[(b*64+t)*64 + s];
        }
        __syncthreads();

        for (int kres = 1; kres >= 0; kres--) {
            const float* dmh = kres ? d_mh1 : d_mh0;
            const float* dm  = kres ? d_m1  : d_m0;
            const float* rw2 = kres ? rw2b : rw2a;
            const float* w1p = d_w1p + kres*24576;
            {
                int r = t >> 3, row = t & 7;
                float acc[8];
                #pragma unroll
                for (int q = 0; q < 8; q++) acc[q] = 0.f;
                for (int ci = 0; ci < 64; ci++) {
                    float w = __ldg(rw2 + ci*32 + r);
                    float xr[12]; ldrow12(gs + ci*120 + (row+1)*12, xr);
                    #pragma unroll
                    for (int q = 0; q < 8; q++) acc[q] += w*xr[q+1];
                }
                const float* mh = dmh + (b*32+r)*64 + row*8;
                float* ar = as_ + r*120 + (row+1)*12 + 1;
                #pragma unroll
                for (int q = 0; q < 8; q++) ar[q] = acc[q]*mh[q];
            }
            __syncthreads();
            #pragma unroll
            for (int half = 0; half < 2; half++) {
                int ci = (t >> 3) + half*32, row = t & 7;
                float acc[8];
                #pragma unroll
                for (int q = 0; q < 8; q++) acc[q] = 0.f;
                for (int r = 0; r < 32; r++) {
                    #pragma unroll
                    for (int dy = 0; dy < 3; dy++) {
                        float xr[12]; ldrow12(as_ + r*120 + (row-dy+2)*12, xr);
                        float4 w = __ldg((const float4*)(w1p + (r*64+ci)*12 + dy*4));
                        #pragma unroll
                        for (int q = 0; q < 8; q++)
                            acc[q] += w.x*xr[q+2] + w.y*xr[q+1] + w.z*xr[q];
                    }
                }
                const float* m = dm + (b*64+ci)*64 + row*8;
                float* gr = gs + ci*120 + (row+1)*12 + 1;
                #pragma unroll
                for (int q = 0; q < 8; q++) gr[q] += acc[q]*m[q];
            }
            __syncthreads();
        }

        if (t < 64) {
            int qy = t >> 3, qx = t & 7;
            float acc = 0.f;
            for (int co = 0; co < 64; co++) {
                const float* gb = gs + co*120;
                const float* ws = d_wsum + co*9;
                #pragma unroll
                for (int dy = 0; dy < 3; dy++) {
                    const float* gr = gb + (qy-dy+2)*12 + 2;
                    acc += ws[dy*3+0]*gr[qx] + ws[dy*3+1]*gr[qx-1] + ws[dy*3+2]*gr[qx-2];
                }
            }
            d_etot[(b*64+s)*64 + t] = acc;
        }
    } else {
        // ======== tangent body ========
        float* ts  = sm;           // [64][64]
        float* tm  = ts + 4096;    // [64][120]
        float* tas = tm + 7680;    // [32][64]
        float* xv  = tas + 2048;   // 64
        int i = blockIdx.x;
        int iy = i >> 3, ix = i & 7;

        for (int k = t; k < 4096; k += 256) ts[k] = 0.f;
        for (int k = t; k < 7680; k += 256) tm[k] = 0.f;
        if (t < 64) xv[t] = x[(b*64+t)*64 + i];
        __syncthreads();

        for (int task = t; task < 576; task += 256) {
            int co = task/9, d = task%9, dy = d/3, dx = d%3;
            int py = iy + 1 - dy, px = ix + 1 - dx;
            if (py >= 0 && py < 8 && px >= 0 && px < 8) {
                float acc = 0.f;
                for (int ci = 0; ci < 64; ci++) acc += __ldg(w1c + ((co*64+ci)*3+dy)*3+dx)*xv[ci];
                ts[co*64 + py*8 + px] = acc;
            }
        }
        __syncthreads();

        for (int kres = 0; kres < 2; kres++) {
            const float* dmh = kres ? d_mh1 : d_mh0;
            const float* dm  = kres ? d_m1  : d_m0;
            const float* rw2 = kres ? rw2b : rw2a;
            const float* w1p = d_w1p + kres*24576;
            for (int k = t; k < 4096; k += 256) {
                int ci = k >> 6, p = k & 63;
                tm[ci*120 + PA12(p>>3, p&7)] = ts[k]*dm[(b*64+ci)*64 + p];
            }
            __syncthreads();
            {
                int r = t >> 3, row = t & 7;
                float acc[8];
                #pragma unroll
                for (int q = 0; q < 8; q++) acc[q] = 0.f;
                for (int ci = 0; ci < 64; ci++) {
                    const float* xb = tm + ci*120;
                    #pragma unroll
                    for (int dy = 0; dy < 3; dy++) {
                        float xr[12]; ldrow12(xb + (row+dy)*12, xr);
                        float4 w = __ldg((const float4*)(w1p + (r*64+ci)*12 + dy*4));
                        #pragma unroll
                        for (int q = 0; q < 8; q++)
                            acc[q] += w.x*xr[q] + w.y*xr[q+1] + w.z*xr[q+2];
                    }
                }
                const float* mh = dmh + (b*32+r)*64 + row*8;
                #pragma unroll
                for (int q = 0; q < 8; q++) tas[r*64 + row*8 + q] = acc[q]*mh[q];
            }
            __syncthreads();
            for (int k = t; k < 4096; k += 256) {
                int p = k & 63;
                float acc = 0.f;
                const float* rwb = rw2 + (k >> 6)*32;
                #pragma unroll
                for (int rr = 0; rr < 8; rr++) {
                    float4 w = __ldg((const float4*)(rwb + rr*4));
                    acc += w.x*tas[(rr*4+0)*64+p] + w.y*tas[(rr*4+1)*64+p]
                         + w.z*tas[(rr*4+2)*64+p] + w.w*tas[(rr*4+3)*64+p];
                }
                ts[k] += acc;
            }
            __syncthreads();
        }

        for (int k = t; k < 4096; k += 256) {
            int ci = k >> 6, p = k & 63;
            tm[k] = ts[k]*d_m2[(b*64+ci)*64 + p];
        }
        __syncthreads();
        for (int k = t; k < 2048; k += 256) {
            int o = k >> 6, p = k & 63;
            float acc = 0.f;
            #pragma unroll
            for (int cc = 0; cc < 16; cc++) {
                float4 w = __ldg((const float4*)(w2c + o*64 + cc*4));
                acc += w.x*tm[(cc*4+0)*64+p] + w.y*tm[(cc*4+1)*64+p]
                     + w.z*tm[(cc*4+2)*64+p] + w.w*tm[(cc*4+3)*64+p];
            }
            d_V[((b*64+i)*32 + o)*64 + p] = acc;
        }
    }
}

// ---- kernel 3: argmin + gather + scatter -> d_ym. grid 8, 256 thr ----
__global__ void __launch_bounds__(256) route_kernel()
{
    __shared__ float Us[64*32];
    __shared__ int ix[64];
    int b = blockIdx.x, t = threadIdx.x;

    if (t < 64) {
        float best = d_etot[(b*64+0)*64 + t]; int bi = 0;
        for (int s = 1; s < 64; s++) {
            float v = d_etot[(b*64+s)*64 + t];
            if (v < best) { best = v; bi = s; }
        }
        ix[t] = bi;
    }
    __syncthreads();
    for (int k = t; k < 2048; k += 256) {
        int i = k >> 5, o = k & 31;
        Us[k] = d_V[((b*64+i)*32 + o)*64 + ix[i]];
    }
    __syncthreads();
    for (int k = t; k < 2048; k += 256) {
        int o = k >> 6, m = k & 63;
        float acc = 0.f;
        for (int ii = 0; ii < 64; ii++)
            acc += (ix[ii] == m) ? Us[ii*32 + o] : 0.f;
        d_ym[b*2048 + o*64 + m] = acc;
    }
}

extern "C" void kernel_launch(void* const* d_in, const int* in_sizes, int n_in,
                              void* d_out, int out_size)
{
    const float* x    = (const float*)d_in[0];
    const float* w1c  = (const float*)d_in[1];
    const float* b1   = (const float*)d_in[2];
    const float* rw1a = (const float*)d_in[3];
    const float* rw2a = (const float*)d_in[4];
    const float* rw1b = (const float*)d_in[5];
    const float* rw2b = (const float*)d_in[6];
    const float* w2c  = (const float*)d_in[7];
    const float* b2   = (const float*)d_in[8];
    const float* pats = (const float*)d_in[9];
    float* out = (float*)d_out;

    const int FWD  = 17920*4;            // 71.7 KB
    const int SEED = 13888*4;            // 55.5 KB -> 4 CTAs/SM
    const int HOP  = (16384 + 8*1056)*4; // 97.8 KB
    cudaFuncSetAttribute(fwd_kernel,  cudaFuncAttributeMaxDynamicSharedMemorySize, FWD);
    cudaFuncSetAttribute(seed_kernel, cudaFuncAttributeMaxDynamicSharedMemorySize, SEED);
    cudaFuncSetAttribute(hop_kernel,  cudaFuncAttributeMaxDynamicSharedMemorySize, HOP);

    float* p_r2; cudaGetSymbolAddress((void**)&p_r2, d_r2);
    float* p_yo; cudaGetSymbolAddress((void**)&p_yo, d_yo);
    float* p_ym; cudaGetSymbolAddress((void**)&p_ym, d_ym);

    prep_kernel<<<192, 256>>>(w1c, rw1a, rw1b);
    fwd_kernel<<<8, 512, FWD>>>(x, b1, rw2a, rw2b, w2c, b2);
    hop_kernel<<<64, 256, HOP>>>(p_yo, pats, p_r2, 0);
    seed_kernel<<<dim3(64,8,2), 256, SEED>>>(x, w1c, rw2a, rw2b, w2c);
    route_kernel<<<8, 256>>>();
    hop_kernel<<<64, 256, HOP>>>(p_ym, pats, out, 1);
}

// round 7
// speedup vs baseline: 1.8012x; 1.0708x over previous
#include <cuda_runtime.h>
#include <math.h>

#define PA12(py,px) (((py)+1)*12 + (px) + 1)

__device__ float d_m0[8*64*64];
__device__ float d_m1[8*64*64];
__device__ float d_m2[8*64*64];
__device__ float d_mh0[8*32*64];
__device__ float d_mh1[8*32*64];
__device__ float d_r2[8*32*64];
__device__ float d_yo[8*32*64];
__device__ float d_ym[8*32*64];
__device__ float d_wsum[64*9];
__device__ float d_etot[8*64*64];
__device__ float d_V[8*64*32*64];     // [b][i][o][p]
__device__ float d_w1p[2*32*64*12];
__device__ float d_w1cp[64*64*12];

__device__ __forceinline__ void ldrow12(const float* p, float* r) {
    float4 a = *(const float4*)p;
    float4 b = *(const float4*)(p + 4);
    float4 c = *(const float4*)(p + 8);
    r[0]=a.x; r[1]=a.y; r[2]=a.z; r[3]=a.w;
    r[4]=b.x; r[5]=b.y; r[6]=b.z; r[7]=b.w;
    r[8]=c.x; r[9]=c.y; r[10]=c.z; r[11]=c.w;
}

// ---- prep ----
__global__ void __launch_bounds__(256) prep_kernel(const float* w1c, const float* rw1a, const float* rw1b)
{
    int t = blockIdx.x*blockDim.x + threadIdx.x;
    if (t < 49152) {
        int rem = t % 12, base = t / 12, dy = rem >> 2, dx = rem & 3;
        d_w1cp[t] = (dx < 3) ? w1c[base*9 + dy*3 + dx] : 0.f;
    }
    if (t < 24576) {
        int rem = t % 12, base = t / 12, dy = rem >> 2, dx = rem & 3;
        d_w1p[t]         = (dx < 3) ? rw1a[base*9 + dy*3 + dx] : 0.f;
        d_w1p[24576 + t] = (dx < 3) ? rw1b[base*9 + dy*3 + dx] : 0.f;
    }
    if (t < 576) {
        int co = t/9, k = t%9; float s = 0.f;
        for (int ci = 0; ci < 64; ci++) s += w1c[(co*64+ci)*9 + k];
        d_wsum[t] = s;
    }
}

// ---- hopfield: grid 64, 256 thr, one warp per pixel ----
__global__ void __launch_bounds__(256) hop_kernel(const float* __restrict__ src,
                                                  const float* __restrict__ pats,
                                                  float* __restrict__ dst, int mode)
{
    extern __shared__ float sm[];
    float* ps  = sm;            // [512][32]
    float* red = ps + 16384;    // [8][32][33]
    int t = threadIdx.x, lane = t & 31, wid = t >> 5;
    int b = blockIdx.x >> 3, p = (blockIdx.x & 7)*8 + wid;

    for (int i = t; i < 16384; i += 256) ps[i] = pats[i];
    __syncthreads();

    const float* yb = src + b*2048;
    float yv[32];
    #pragma unroll
    for (int c = 0; c < 32; c++) yv[c] = yb[c*64 + p];

    float le[16], mx = -3.4e38f;
    #pragma unroll
    for (int k = 0; k < 16; k++) {
        const float* pr = ps + (lane + 32*k)*32;
        float a = 0.f;
        #pragma unroll
        for (int c = 0; c < 32; c++) a = fmaf(yv[c], pr[c], a);
        a *= 0.17677669529663688f;
        le[k] = a; mx = fmaxf(mx, a);
    }
    #pragma unroll
    for (int o = 16; o > 0; o >>= 1) mx = fmaxf(mx, __shfl_xor_sync(~0u, mx, o));

    float ssum = 0.f, accq[32];
    #pragma unroll
    for (int c = 0; c < 32; c++) accq[c] = 0.f;
    #pragma unroll
    for (int k = 0; k < 16; k++) {
        float pe = expf(le[k] - mx);
        ssum += pe;
        const float* pr = ps + (lane + 32*k)*32;
        #pragma unroll
        for (int c = 0; c < 32; c++) accq[c] = fmaf(pe, pr[c], accq[c]);
    }
    #pragma unroll
    for (int o = 16; o > 0; o >>= 1) ssum += __shfl_xor_sync(~0u, ssum, o);

    float* rw = red + wid*1056;
    #pragma unroll
    for (int c = 0; c < 32; c++) rw[lane*33 + c] = accq[c];
    __syncwarp();
    float colsum = 0.f;
    #pragma unroll
    for (int l = 0; l < 32; l++) colsum += rw[l*33 + lane];
    float q = colsum / ssum;

    if (mode == 0) dst[b*2048 + lane*64 + p] = 2.f*(yv[lane] - q);
    else           dst[b*2048 + lane*64 + p] = q;
}

// ---- kernel 1: forward conv stack, masks, yo. grid 8, 512 thr ----
__global__ void __launch_bounds__(512, 1) fwd_kernel(
                           const float* x, const float* b1,
                           const float* rw2a, const float* rw2b,
                           const float* w2c, const float* b2)
{
    extern __shared__ float sm[];
    float* xs   = sm;            // [64][120]
    float* ys   = xs + 7680;     // [64][64]
    float* hs   = ys + 4096;     // [32][64]
    float* part = hs + 2048;     // [4][2048] (conv1 uses [2][4096])
    int b = blockIdx.x, t = threadIdx.x;

    for (int i = t; i < 7680; i += 512) xs[i] = 0.f;
    __syncthreads();
    for (int i = t; i < 4096; i += 512) {
        int ci = i >> 6, p = i & 63;
        xs[ci*120 + PA12(p>>3, p&7)] = x[(b*64 + ci)*64 + p];
    }
    __syncthreads();

    { // conv1 3x3 pad1 64->64: 2co-tile x 2-way ci split
        int half = t >> 8, cp = (t >> 3) & 31, row = t & 7;
        int co0 = 2*cp, co1 = co0 + 1;
        float a0[8], a1[8];
        #pragma unroll
        for (int q = 0; q < 8; q++) { a0[q] = 0.f; a1[q] = 0.f; }
        for (int cc = 0; cc < 32; cc++) {
            int ci = half*32 + cc;
            const float* xb = xs + ci*120;
            #pragma unroll
            for (int dy = 0; dy < 3; dy++) {
                float xr[12]; ldrow12(xb + (row+dy)*12, xr);
                float4 w0 = __ldg((const float4*)(d_w1cp + (co0*64+ci)*12 + dy*4));
                float4 w1 = __ldg((const float4*)(d_w1cp + (co1*64+ci)*12 + dy*4));
                #pragma unroll
                for (int q = 0; q < 8; q++) {
                    a0[q] += w0.x*xr[q] + w0.y*xr[q+1] + w0.z*xr[q+2];
                    a1[q] += w1.x*xr[q] + w1.y*xr[q+1] + w1.z*xr[q+2];
                }
            }
        }
        #pragma unroll
        for (int q = 0; q < 8; q++) {
            part[half*4096 + co0*64 + row*8 + q] = a0[q];
            part[half*4096 + co1*64 + row*8 + q] = a1[q];
        }
    }
    __syncthreads();
    for (int i = t; i < 4096; i += 512) {
        int ci = i >> 6, p = i & 63;
        float v = part[i] + part[4096 + i] + b1[ci];
        ys[i] = v;
        float m = v > 0.f ? 1.f : 0.f;
        d_m0[(b*64+ci)*64 + p] = m;
        xs[ci*120 + PA12(p>>3, p&7)] = v*m;
    }
    __syncthreads();

    for (int kres = 0; kres < 2; kres++) {
        const float* rw2 = kres ? rw2b : rw2a;
        const float* w1p = d_w1p + kres*24576;
        float* dmh = kres ? d_mh1 : d_mh0;
        float* dm  = kres ? d_m2  : d_m1;
        { // conv3x3 64->32: 2r-tile x 4-way ci split
            int qt = t >> 7, rp = (t >> 3) & 15, row = t & 7;
            int r0 = 2*rp, r1 = r0 + 1;
            float a0[8], a1[8];
            #pragma unroll
            for (int q = 0; q < 8; q++) { a0[q] = 0.f; a1[q] = 0.f; }
            for (int cc = 0; cc < 16; cc++) {
                int ci = qt*16 + cc;
                const float* xb = xs + ci*120;
                #pragma unroll
                for (int dy = 0; dy < 3; dy++) {
                    float xr[12]; ldrow12(xb + (row+dy)*12, xr);
                    float4 w0 = __ldg((const float4*)(w1p + (r0*64+ci)*12 + dy*4));
                    float4 w1 = __ldg((const float4*)(w1p + (r1*64+ci)*12 + dy*4));
                    #pragma unroll
                    for (int q = 0; q < 8; q++) {
                        a0[q] += w0.x*xr[q] + w0.y*xr[q+1] + w0.z*xr[q+2];
                        a1[q] += w1.x*xr[q] + w1.y*xr[q+1] + w1.z*xr[q+2];
                    }
                }
            }
            #pragma unroll
            for (int q = 0; q < 8; q++) {
                part[qt*2048 + r0*64 + row*8 + q] = a0[q];
                part[qt*2048 + r1*64 + row*8 + q] = a1[q];
            }
        }
        __syncthreads();
        for (int k = t; k < 2048; k += 512) {
            float v = part[k] + part[2048+k] + part[4096+k] + part[6144+k];
            int r = k >> 6, p = k & 63;
            float m = v > 0.f ? 1.f : 0.f;
            dmh[(b*32+r)*64 + p] = m;
            hs[k] = v*m;
        }
        __syncthreads();
        for (int k = t; k < 4096; k += 512) {
            int ci = k >> 6, p = k & 63;
            float acc = ys[k];
            #pragma unroll
            for (int rr = 0; rr < 8; rr++) {
                float4 w = __ldg((const float4*)(rw2 + ci*32 + rr*4));
                acc += w.x*hs[(rr*4+0)*64+p] + w.y*hs[(rr*4+1)*64+p]
                     + w.z*hs[(rr*4+2)*64+p] + w.w*hs[(rr*4+3)*64+p];
            }
            ys[k] = acc;
        }
        __syncthreads();
        for (int k = t; k < 4096; k += 512) {
            int ci = k >> 6, p = k & 63;
            float v = ys[k], m = v > 0.f ? 1.f : 0.f;
            dm[(b*64+ci)*64 + p] = m;
            xs[ci*120 + PA12(p>>3, p&7)] = v*m;
        }
        __syncthreads();
    }

    for (int k = t; k < 2048; k += 512) { // conv2 1x1 + bias -> global yo
        int o = k >> 6, p = k & 63;
        float acc = b2[o];
        int pa = PA12(p>>3, p&7);
        #pragma unroll
        for (int cc = 0; cc < 16; cc++) {
            float4 w = __ldg((const float4*)(w2c + o*64 + cc*4));
            acc += w.x*xs[(cc*4+0)*120+pa] + w.y*xs[(cc*4+1)*120+pa]
                 + w.z*xs[(cc*4+2)*120+pa] + w.w*xs[(cc*4+3)*120+pa];
        }
        d_yo[b*2048 + k] = acc;
    }
}

// ---- kernel 2: merged per-seed backward (z=0) + tangent (z=1). grid (64,8,2), 256 thr ----
__global__ void __launch_bounds__(256, 4) seed_kernel(
                           const float* x, const float* w1c,
                           const float* rw2a, const float* rw2b, const float* w2c)
{
    extern __shared__ float sm[];
    int t = threadIdx.x, b = blockIdx.y;

    if (blockIdx.z == 0) {
        // ======== backward body ========
        float* gs  = sm;           // [64][120]
        float* as_ = gs + 7680;    // [32][120]
        int s = blockIdx.x;

        for (int i = t; i < 7680; i += 256) gs[i] = 0.f;
        for (int i = t; i < 3840; i += 256) as_[i] = 0.f;
        __syncthreads();

        if (t < 64) {
            float acc = 0.f;
            for (int o = 0; o < 32; o++) acc += d_r2[(b*32+o)*64 + s] * __ldg(w2c + o*64 + t);
            gs[t*120 + PA12(s>>3, s&7)] = acc * d_m2[(b*64+t)*64 + s];
        }
        __syncthreads();

        for (int kres = 1; kres >= 0; kres--) {
            const float* dmh = kres ? d_mh1 : d_mh0;
            const float* dm  = kres ? d_m1  : d_m0;
            const float* rw2 = kres ? rw2b : rw2a;
            const float* w1p = d_w1p + kres*24576;
            if (t < 128) { // a[r,p] = mh * W2^T g : 2r-tile
                int rp = t >> 3, row = t & 7;
                int r0 = 2*rp, r1 = r0 + 1;
                float a0[8], a1[8];
                #pragma unroll
                for (int q = 0; q < 8; q++) { a0[q] = 0.f; a1[q] = 0.f; }
                for (int ci = 0; ci < 64; ci++) {
                    float2 wv = __ldg((const float2*)(rw2 + ci*32 + rp*2));
                    float xr[12]; ldrow12(gs + ci*120 + (row+1)*12, xr);
                    #pragma unroll
                    for (int q = 0; q < 8; q++) {
                        a0[q] += wv.x*xr[q+1];
                        a1[q] += wv.y*xr[q+1];
                    }
                }
                const float* mh0 = dmh + (b*32+r0)*64 + row*8;
                const float* mh1 = dmh + (b*32+r1)*64 + row*8;
                float* ar0 = as_ + r0*120 + (row+1)*12 + 1;
                float* ar1 = as_ + r1*120 + (row+1)*12 + 1;
                #pragma unroll
                for (int q = 0; q < 8; q++) { ar0[q] = a0[q]*mh0[q]; ar1[q] = a1[q]*mh1[q]; }
            }
            __syncthreads();
            { // g += m * W1^T a : 2ci-tile, all 256 thr
                int cp = t >> 3, row = t & 7;
                int ci0 = 2*cp, ci1 = ci0 + 1;
                float a0[8], a1[8];
                #pragma unroll
                for (int q = 0; q < 8; q++) { a0[q] = 0.f; a1[q] = 0.f; }
                for (int r = 0; r < 32; r++) {
                    #pragma unroll
                    for (int dy = 0; dy < 3; dy++) {
                        float xr[12]; ldrow12(as_ + r*120 + (row-dy+2)*12, xr);
                        float4 w0 = __ldg((const float4*)(w1p + (r*64+ci0)*12 + dy*4));
                        float4 w1 = __ldg((const float4*)(w1p + (r*64+ci1)*12 + dy*4));
                        #pragma unroll
                        for (int q = 0; q < 8; q++) {
                            a0[q] += w0.x*xr[q+2] + w0.y*xr[q+1] + w0.z*xr[q];
                            a1[q] += w1.x*xr[q+2] + w1.y*xr[q+1] + w1.z*xr[q];
                        }
                    }
                }
                const float* m0 = dm + (b*64+ci0)*64 + row*8;
                const float* m1 = dm + (b*64+ci1)*64 + row*8;
                float* g0 = gs + ci0*120 + (row+1)*12 + 1;
                float* g1 = gs + ci1*120 + (row+1)*12 + 1;
                #pragma unroll
                for (int q = 0; q < 8; q++) { g0[q] += a0[q]*m0[q]; g1[q] += a1[q]*m1[q]; }
            }
            __syncthreads();
        }

        if (t < 64) {
            int qy = t >> 3, qx = t & 7;
            float acc = 0.f;
            for (int co = 0; co < 64; co++) {
                const float* gb = gs + co*120;
                const float* ws = d_wsum + co*9;
                #pragma unroll
                for (int dy = 0; dy < 3; dy++) {
                    const float* gr = gb + (qy-dy+2)*12 + 2;
                    acc += ws[dy*3+0]*gr[qx] + ws[dy*3+1]*gr[qx-1] + ws[dy*3+2]*gr[qx-2];
                }
            }
            d_etot[(b*64+s)*64 + t] = acc;
        }
    } else {
        // ======== tangent body ========
        float* ts  = sm;           // [64][64]
        float* tm  = ts + 4096;    // [64][120]
        float* tas = tm + 7680;    // [32][64]
        float* xv  = tas + 2048;   // 64
        int i = blockIdx.x;
        int iy = i >> 3, ix = i & 7;

        for (int k = t; k < 4096; k += 256) ts[k] = 0.f;
        for (int k = t; k < 7680; k += 256) tm[k] = 0.f;
        if (t < 64) xv[t] = x[(b*64+t)*64 + i];
        __syncthreads();

        for (int task = t; task < 576; task += 256) {
            int co = task/9, d = task%9, dy = d/3, dx = d%3;
            int py = iy + 1 - dy, px = ix + 1 - dx;
            if (py >= 0 && py < 8 && px >= 0 && px < 8) {
                float acc = 0.f;
                for (int ci = 0; ci < 64; ci++) acc += __ldg(w1c + ((co*64+ci)*3+dy)*3+dx)*xv[ci];
                ts[co*64 + py*8 + px] = acc;
            }
        }
        __syncthreads();

        for (int kres = 0; kres < 2; kres++) {
            const float* dmh = kres ? d_mh1 : d_mh0;
            const float* dm  = kres ? d_m1  : d_m0;
            const float* rw2 = kres ? rw2b : rw2a;
            const float* w1p = d_w1p + kres*24576;
            for (int k = t; k < 4096; k += 256) {
                int ci = k >> 6, p = k & 63;
                tm[ci*120 + PA12(p>>3, p&7)] = ts[k]*dm[(b*64+ci)*64 + p];
            }
            __syncthreads();
            if (t < 128) { // tas = mh * conv3x3(tm): 2r-tile
                int rp = t >> 3, row = t & 7;
                int r0 = 2*rp, r1 = r0 + 1;
                float a0[8], a1[8];
                #pragma unroll
                for (int q = 0; q < 8; q++) { a0[q] = 0.f; a1[q] = 0.f; }
                for (int ci = 0; ci < 64; ci++) {
                    const float* xb = tm + ci*120;
                    #pragma unroll
                    for (int dy = 0; dy < 3; dy++) {
                        float xr[12]; ldrow12(xb + (row+dy)*12, xr);
                        float4 w0 = __ldg((const float4*)(w1p + (r0*64+ci)*12 + dy*4));
                        float4 w1 = __ldg((const float4*)(w1p + (r1*64+ci)*12 + dy*4));
                        #pragma unroll
                        for (int q = 0; q < 8; q++) {
                            a0[q] += w0.x*xr[q] + w0.y*xr[q+1] + w0.z*xr[q+2];
                            a1[q] += w1.x*xr[q] + w1.y*xr[q+1] + w1.z*xr[q+2];
                        }
                    }
                }
                const float* mh0 = dmh + (b*32+r0)*64 + row*8;
                const float* mh1 = dmh + (b*32+r1)*64 + row*8;
                #pragma unroll
                for (int q = 0; q < 8; q++) {
                    tas[r0*64 + row*8 + q] = a0[q]*mh0[q];
                    tas[r1*64 + row*8 + q] = a1[q]*mh1[q];
                }
            }
            __syncthreads();
            for (int k = t; k < 2048; k += 256) { // ts += W2 @ tas: 2ci-tile
                int cp = k >> 6, p = k & 63;
                int ci0 = 2*cp, ci1 = ci0 + 1;
                float a0 = 0.f, a1 = 0.f;
                #pragma unroll
                for (int rr = 0; rr < 8; rr++) {
                    float4 w0 = __ldg((const float4*)(rw2 + ci0*32 + rr*4));
                    float4 w1 = __ldg((const float4*)(rw2 + ci1*32 + rr*4));
                    float t0 = tas[(rr*4+0)*64+p], t1 = tas[(rr*4+1)*64+p];
                    float t2 = tas[(rr*4+2)*64+p], t3 = tas[(rr*4+3)*64+p];
                    a0 += w0.x*t0 + w0.y*t1 + w0.z*t2 + w0.w*t3;
                    a1 += w1.x*t0 + w1.y*t1 + w1.z*t2 + w1.w*t3;
                }
                ts[ci0*64 + p] += a0;
                ts[ci1*64 + p] += a1;
            }
            __syncthreads();
        }

        for (int k = t; k < 4096; k += 256) {
            int ci = k >> 6, p = k & 63;
            tm[k] = ts[k]*d_m2[(b*64+ci)*64 + p];
        }
        __syncthreads();
        for (int k = t; k < 1024; k += 256) { // V epilogue: 2o-tile
            int op = k >> 6, p = k & 63;
            int o0 = 2*op, o1 = o0 + 1;
            float a0 = 0.f, a1 = 0.f;
            #pragma unroll
            for (int cc = 0; cc < 16; cc++) {
                float4 w0 = __ldg((const float4*)(w2c + o0*64 + cc*4));
                float4 w1 = __ldg((const float4*)(w2c + o1*64 + cc*4));
                float t0 = tm[(cc*4+0)*64+p], t1 = tm[(cc*4+1)*64+p];
                float t2 = tm[(cc*4+2)*64+p], t3 = tm[(cc*4+3)*64+p];
                a0 += w0.x*t0 + w0.y*t1 + w0.z*t2 + w0.w*t3;
                a1 += w1.x*t0 + w1.y*t1 + w1.z*t2 + w1.w*t3;
            }
            d_V[((b*64+i)*32 + o0)*64 + p] = a0;
            d_V[((b*64+i)*32 + o1)*64 + p] = a1;
        }
    }
}

// ---- kernel 3: argmin + gather + scatter -> d_ym. grid 8, 256 thr ----
__global__ void __launch_bounds__(256) route_kernel()
{
    __shared__ float Us[64*32];
    __shared__ int ix[64];
    int b = blockIdx.x, t = threadIdx.x;

    if (t < 64) {
        float best = d_etot[(b*64+0)*64 + t]; int bi = 0;
        for (int s = 1; s < 64; s++) {
            float v = d_etot[(b*64+s)*64 + t];
            if (v < best) { best = v; bi = s; }
        }
        ix[t] = bi;
    }
    __syncthreads();
    for (int k = t; k < 2048; k += 256) {
        int i = k >> 5, o = k & 31;
        Us[k] = d_V[((b*64+i)*32 + o)*64 + ix[i]];
    }
    __syncthreads();
    for (int k = t; k < 2048; k += 256) {
        int o = k >> 6, m = k & 63;
        float acc = 0.f;
        for (int ii = 0; ii < 64; ii++)
            acc += (ix[ii] == m) ? Us[ii*32 + o] : 0.f;
        d_ym[b*2048 + o*64 + m] = acc;
    }
}

extern "C" void kernel_launch(void* const* d_in, const int* in_sizes, int n_in,
                              void* d_out, int out_size)
{
    const float* x    = (const float*)d_in[0];
    const float* w1c  = (const float*)d_in[1];
    const float* b1   = (const float*)d_in[2];
    const float* rw1a = (const float*)d_in[3];
    const float* rw2a = (const float*)d_in[4];
    const float* rw1b = (const float*)d_in[5];
    const float* rw2b = (const float*)d_in[6];
    const float* w2c  = (const float*)d_in[7];
    const float* b2   = (const float*)d_in[8];
    const float* pats = (const float*)d_in[9];
    float* out = (float*)d_out;

    const int FWD  = 22016*4;            // 88 KB
    const int SEED = 13888*4;            // 55.5 KB -> 4 CTAs/SM
    const int HOP  = (16384 + 8*1056)*4; // 97.8 KB
    cudaFuncSetAttribute(fwd_kernel,  cudaFuncAttributeMaxDynamicSharedMemorySize, FWD);
    cudaFuncSetAttribute(seed_kernel, cudaFuncAttributeMaxDynamicSharedMemorySize, SEED);
    cudaFuncSetAttribute(hop_kernel,  cudaFuncAttributeMaxDynamicSharedMemorySize, HOP);

    float* p_r2; cudaGetSymbolAddress((void**)&p_r2, d_r2);
    float* p_yo; cudaGetSymbolAddress((void**)&p_yo, d_yo);
    float* p_ym; cudaGetSymbolAddress((void**)&p_ym, d_ym);

    prep_kernel<<<192, 256>>>(w1c, rw1a, rw1b);
    fwd_kernel<<<8, 512, FWD>>>(x, b1, rw2a, rw2b, w2c, b2);
    hop_kernel<<<64, 256, HOP>>>(p_yo, pats, p_r2, 0);
    seed_kernel<<<dim3(64,8,2), 256, SEED>>>(x, w1c, rw2a, rw2b, w2c);
    route_kernel<<<8, 256>>>();
    hop_kernel<<<64, 256, HOP>>>(p_ym, pats, out, 1);
}